// round 13
// baseline (speedup 1.0000x reference)
#include <cuda_runtime.h>
#include <cuda_bf16.h>
#include <math.h>

#define Bc 2
#define Tc 4096
#define Ec 1024
#define Hc 16
#define Dc 64
#define Pc 64
#define PMc 512
#define CHc 128
#define NCc 32
#define BHc 32

typedef unsigned long long u64;
typedef unsigned int u32;

// ---------------- scratch (device globals; no allocations allowed) ----------
__device__ float g_qkv[(size_t)Bc*Tc*3*Ec];
__device__ float g_ckv[(size_t)BHc*NCc*PMc*Dc];
__device__ float g_ks [(size_t)BHc*NCc*PMc];
__device__ float g_o  [(size_t)BHc*Tc*Dc];
__device__ float g_nrm[(size_t)BHc*Tc];
// bf16 features (hi only), [bhc][token 128][feature 512]
__device__ __align__(16) __nv_bfloat16 g_qf[(size_t)BHc*NCc*CHc*PMc];
__device__ __align__(16) __nv_bfloat16 g_kf[(size_t)BHc*NCc*CHc*PMc];
// bf16 hi/lo exclusive kv state, [bhc][f][d]
__device__ __align__(16) __nv_bfloat16 g_ckvh[(size_t)BHc*NCc*PMc*Dc];
__device__ __align__(16) __nv_bfloat16 g_ckvl[(size_t)BHc*NCc*PMc*Dc];
// bf16 split operands for dense GEMMs
__device__ __align__(16) __nv_bfloat16 g_ah[(size_t)Bc*Tc*Ec];
__device__ __align__(16) __nv_bfloat16 g_al[(size_t)Bc*Tc*Ec];
__device__ __align__(16) __nv_bfloat16 g_wh[(size_t)3*Ec*Ec];
__device__ __align__(16) __nv_bfloat16 g_wl[(size_t)3*Ec*Ec];
__device__ __align__(16) __nv_bfloat16 g_w2h[(size_t)Ec*Ec];
__device__ __align__(16) __nv_bfloat16 g_w2l[(size_t)Ec*Ec];

// ================= helpers ===================================================
__device__ __forceinline__ u32 smem_u32(const void* p) {
    u32 a; asm("{ .reg .u64 t; cvta.to.shared.u64 t, %1; cvt.u32.u64 %0, t; }"
               : "=r"(a) : "l"(p));
    return a;
}
#define CP_ASYNC16(dst, src) \
    asm volatile("cp.async.cg.shared.global [%0], [%1], 16;\n" :: "r"(dst), "l"(src))
#define CP_COMMIT() asm volatile("cp.async.commit_group;\n" ::: "memory")
#define CP_WAIT1()  asm volatile("cp.async.wait_group 1;\n" ::: "memory")
#define CP_WAIT0()  asm volatile("cp.async.wait_group 0;\n" ::: "memory")

__device__ __forceinline__ void ldsm4(u32 &r0, u32 &r1, u32 &r2, u32 &r3, u32 a) {
    asm volatile("ldmatrix.sync.aligned.m8n8.x4.shared.b16 {%0,%1,%2,%3}, [%4];\n"
                 : "=r"(r0), "=r"(r1), "=r"(r2), "=r"(r3) : "r"(a));
}
__device__ __forceinline__ void ldsm4t(u32 &r0, u32 &r1, u32 &r2, u32 &r3, u32 a) {
    asm volatile("ldmatrix.sync.aligned.m8n8.x4.trans.shared.b16 {%0,%1,%2,%3}, [%4];\n"
                 : "=r"(r0), "=r"(r1), "=r"(r2), "=r"(r3) : "r"(a));
}
__device__ __forceinline__ void mma16816(float* c, const u32* a, u32 b0, u32 b1) {
    asm volatile(
        "mma.sync.aligned.m16n8k16.row.col.f32.bf16.bf16.f32 "
        "{%0,%1,%2,%3},{%4,%5,%6,%7},{%8,%9},{%0,%1,%2,%3};\n"
        : "+f"(c[0]), "+f"(c[1]), "+f"(c[2]), "+f"(c[3])
        : "r"(a[0]), "r"(a[1]), "r"(a[2]), "r"(a[3]), "r"(b0), "r"(b1));
}

// ======== combined fp32 -> bf16 hi/lo split for x, qkv_w, out_w =============
// blocks [0,8192): x -> g_ah/g_al; [8192,11264): qkv_w -> g_wh/g_wl;
// [11264,12288): out_w -> g_w2h/g_w2l
__global__ void split3_bf16_k(const float* __restrict__ x,
                              const float* __restrict__ qkv_w,
                              const float* __restrict__ out_w)
{
    int blk = blockIdx.x;
    const float* s;
    __nv_bfloat16 *h, *l;
    size_t base;
    if (blk < 8192)       { s = x;     h = g_ah;  l = g_al;  base = (size_t)blk*1024; }
    else if (blk < 11264) { s = qkv_w; h = g_wh;  l = g_wl;  base = (size_t)(blk-8192)*1024; }
    else                  { s = out_w; h = g_w2h; l = g_w2l; base = (size_t)(blk-11264)*1024; }
    size_t i = base + (size_t)threadIdx.x*4;
    float4 v = *(const float4*)(s + i);
    __nv_bfloat16 h0=__float2bfloat16(v.x), h1=__float2bfloat16(v.y);
    __nv_bfloat16 h2=__float2bfloat16(v.z), h3=__float2bfloat16(v.w);
    *(__nv_bfloat162*)(h+i)   = {h0,h1};
    *(__nv_bfloat162*)(h+i+2) = {h2,h3};
    *(__nv_bfloat162*)(l+i)   = {__float2bfloat16(v.x-__bfloat162float(h0)),
                                 __float2bfloat16(v.y-__bfloat162float(h1))};
    *(__nv_bfloat162*)(l+i+2) = {__float2bfloat16(v.z-__bfloat162float(h2)),
                                 __float2bfloat16(v.w-__bfloat162float(h3))};
}

// ================= HMMA GEMM: C[M,N] = A @ W^T + bias (bf16x3 split) ========
#define S_STRIDE 40
#define S_ARR 10240
#define S_STAGE 40960

__global__ __launch_bounds__(256, 2)
void gemm_mma_k(const __nv_bfloat16* __restrict__ Abase_h,
                const __nv_bfloat16* __restrict__ Abase_l,
                const __nv_bfloat16* __restrict__ Wbase_h,
                const __nv_bfloat16* __restrict__ Wbase_l,
                const float* __restrict__ bias, float* __restrict__ C, int N)
{
    extern __shared__ char smem[];
    u32 sb = smem_u32(smem);
    const int K = 1024;
    int tid = threadIdx.x;
    int lane = tid & 31, warp = tid >> 5;
    int wm = warp >> 1, wn = warp & 1;
    int bm = blockIdx.y * 128, bn = blockIdx.x * 128;

    const __nv_bfloat16* Ah = Abase_h + (size_t)bm * K;
    const __nv_bfloat16* Al = Abase_l + (size_t)bm * K;
    const __nv_bfloat16* Wh = Wbase_h + (size_t)bn * K;
    const __nv_bfloat16* Wl = Wbase_l + (size_t)bn * K;

    int r0 = (tid*2) >> 2, s0 = (tid*2) & 3;
    int r1 = (tid*2+1) >> 2, s1 = (tid*2+1) & 3;

    int lr = lane & 7;
    int a_row = lr + (((lane >> 3) & 1) << 3);
    int a_col = ((lane >> 4) & 1) << 3;
    int b_row = lr + (((lane >> 4) & 1) << 3);
    int b_col = ((lane >> 3) & 1) << 3;

    float acc[2][8][4];
    #pragma unroll
    for (int i = 0; i < 2; i++)
        #pragma unroll
        for (int j = 0; j < 8; j++)
            #pragma unroll
            for (int q = 0; q < 4; q++) acc[i][j][q] = 0.f;

    auto load_chunk = [&](int ch, int stage) {
        int k0 = ch * 32;
        u32 st = sb + stage * S_STAGE;
        u32 d0 = st + r0*80 + s0*16;
        u32 d1 = st + r1*80 + s1*16;
        CP_ASYNC16(d0, Ah + (size_t)r0*K + k0 + s0*8);
        CP_ASYNC16(d1, Ah + (size_t)r1*K + k0 + s1*8);
        CP_ASYNC16(d0 + S_ARR, Al + (size_t)r0*K + k0 + s0*8);
        CP_ASYNC16(d1 + S_ARR, Al + (size_t)r1*K + k0 + s1*8);
        CP_ASYNC16(d0 + 2*S_ARR, Wh + (size_t)r0*K + k0 + s0*8);
        CP_ASYNC16(d1 + 2*S_ARR, Wh + (size_t)r1*K + k0 + s1*8);
        CP_ASYNC16(d0 + 3*S_ARR, Wl + (size_t)r0*K + k0 + s0*8);
        CP_ASYNC16(d1 + 3*S_ARR, Wl + (size_t)r1*K + k0 + s1*8);
        CP_COMMIT();
    };

    load_chunk(0, 0);

    for (int ch = 0; ch < 32; ch++) {
        int stage = ch & 1;
        if (ch + 1 < 32) { load_chunk(ch + 1, stage ^ 1); CP_WAIT1(); }
        else             { CP_WAIT0(); }
        __syncthreads();

        u32 st = sb + stage * S_STAGE;
        #pragma unroll
        for (int ks = 0; ks < 2; ks++) {
            u32 afh[2][4], afl[2][4], bfh[4][4], bfl[4][4];
            #pragma unroll
            for (int mi = 0; mi < 2; mi++) {
                u32 addr = st + ((wm*32 + mi*16 + a_row)*S_STRIDE + ks*16 + a_col)*2;
                ldsm4(afh[mi][0], afh[mi][1], afh[mi][2], afh[mi][3], addr);
                ldsm4(afl[mi][0], afl[mi][1], afl[mi][2], afl[mi][3], addr + S_ARR);
            }
            #pragma unroll
            for (int nj = 0; nj < 4; nj++) {
                u32 addr = st + 2*S_ARR +
                           ((wn*64 + nj*16 + b_row)*S_STRIDE + ks*16 + b_col)*2;
                ldsm4(bfh[nj][0], bfh[nj][1], bfh[nj][2], bfh[nj][3], addr);
                ldsm4(bfl[nj][0], bfl[nj][1], bfl[nj][2], bfl[nj][3], addr + S_ARR);
            }
            #pragma unroll
            for (int mi = 0; mi < 2; mi++) {
                #pragma unroll
                for (int ni = 0; ni < 8; ni++) {
                    int nj = ni >> 1, off = (ni & 1) << 1;
                    mma16816(acc[mi][ni], afh[mi], bfh[nj][off], bfh[nj][off+1]);
                    mma16816(acc[mi][ni], afh[mi], bfl[nj][off], bfl[nj][off+1]);
                    mma16816(acc[mi][ni], afl[mi], bfh[nj][off], bfh[nj][off+1]);
                }
            }
        }
        __syncthreads();
    }

    #pragma unroll
    for (int mi = 0; mi < 2; mi++) {
        #pragma unroll
        for (int ni = 0; ni < 8; ni++) {
            int m = bm + wm*32 + mi*16 + (lane >> 2);
            int n = bn + wn*64 + ni*8 + (lane & 3)*2;
            float2 o0, o1;
            o0.x = acc[mi][ni][0] + bias[n];
            o0.y = acc[mi][ni][1] + bias[n+1];
            o1.x = acc[mi][ni][2] + bias[n];
            o1.y = acc[mi][ni][3] + bias[n+1];
            *(float2*)(C + (size_t)m*N + n)     = o0;
            *(float2*)(C + (size_t)(m+8)*N + n) = o1;
        }
    }
}

// ---------------- feature map -> bf16 (hi only) [token][feature] ------------
// v4: xs transposed to [d][132] so the poly-dot a[8] loads are 2x LDS.128
#define F_XS   0
#define F_PS   (64*132)
#define F_OM   (F_PS + 64*68)
#define F_PRF  (F_OM + 512)
#define F_RN   (F_PRF + 1024)
#define F_SMEM ((F_RN + 128)*4)

__global__ __launch_bounds__(256, 3) void features_k(
    const float* __restrict__ omega, const float* __restrict__ poly_w,
    const float* __restrict__ qnodes, const float* __restrict__ qweights)
{
    extern __shared__ float fsm[];
    float* xs  = fsm + F_XS;           // [d][132] (token-minor)
    float* ps  = fsm + F_PS;           // [d][68]
    float* om  = fsm + F_OM;
    float* prf = fsm + F_PRF;
    float* rn  = fsm + F_RN;
    int bhc = blockIdx.x;
    int isK = blockIdx.y;
    int bh = bhc >> 5, c = bhc & 31;
    int h = bh & 15, b = bh >> 4;
    const float* src = g_qkv + ((size_t)(b*Tc + c*CHc))*(3*Ec) + isK*Ec + h*64;
    __nv_bfloat16* dh = (isK ? g_kf : g_qf) + (size_t)bhc*CHc*PMc;
    int tid = threadIdx.x;
    #pragma unroll
    for (int l = 0; l < 8; l++) {
        int idx = tid + l*256;
        int i = idx >> 4, dd = (idx & 15) << 2;
        float4 v = *(const float4*)(src + (size_t)i*(3*Ec) + dd);
        xs[(dd+0)*132 + i] = v.x;
        xs[(dd+1)*132 + i] = v.y;
        xs[(dd+2)*132 + i] = v.z;
        xs[(dd+3)*132 + i] = v.w;
    }
    {
        const float* pwp = poly_w + h*4096;
        #pragma unroll
        for (int l = 0; l < 4; l++) {
            int idx = tid + l*256;
            int d = idx >> 4, pc = (idx & 15) << 2;
            *(float4*)&ps[d*68 + pc] = *(const float4*)(pwp + d*64 + pc);
        }
    }
    om[tid]       = omega[h*512 + tid];
    om[tid + 256] = omega[h*512 + tid + 256];
    __syncthreads();
    if (tid < 128) {
        float s = 0.f;
        #pragma unroll
        for (int d = 0; d < 64; d++) { float x = xs[d*132 + tid]; s += x*x; }
        rn[tid] = 1.f / fmaxf(sqrtf(s), 1e-12f);
    }
    __syncthreads();
    float s0 = qnodes[0];
    float sq2s = sqrtf(fmaxf(2.f*s0, 0.f));
    float wq = sqrtf(fmaxf(qweights[0], 0.f));
    float prescale = 0.3535533905932738f * wq;
    #pragma unroll
    for (int l = 0; l < 4; l++) {
        int pair = tid + l*256;
        int i = pair >> 3, m = pair & 7;
        float a = 0.f;
        #pragma unroll
        for (int d = 0; d < 64; d++) a += xs[d*132 + i] * om[d*8 + m];
        float e = fminf(fmaxf(a * rn[i] * sq2s - s0, -20.f), 20.f);
        prf[i*8 + m] = expf(e) * prescale;
    }
    __syncthreads();
    int ti = (tid >> 4) << 3, tp = tid & 15;
    float acc[8][4] = {};
    for (int d = 0; d < 64; d++) {
        float a[8];
        *(float4*)(a)     = *(const float4*)&xs[d*132 + ti];
        *(float4*)(a + 4) = *(const float4*)&xs[d*132 + ti + 4];
        float b0 = ps[d*68 + tp];
        float b1 = ps[d*68 + tp + 16];
        float b2 = ps[d*68 + tp + 32];
        float b3 = ps[d*68 + tp + 48];
        #pragma unroll
        for (int i2 = 0; i2 < 8; i2++) {
            acc[i2][0] += a[i2]*b0; acc[i2][1] += a[i2]*b1;
            acc[i2][2] += a[i2]*b2; acc[i2][3] += a[i2]*b3;
        }
    }
    #pragma unroll
    for (int i2 = 0; i2 < 8; i2++) {
        float r = rn[ti + i2];
        #pragma unroll
        for (int j = 0; j < 4; j++) {
            float t = acc[i2][j] * r;
            acc[i2][j] = t*t*0.125f;
        }
    }
    #pragma unroll
    for (int i2 = 0; i2 < 8; i2++) {
        int tok = ti + i2;
        const float* pr = &prf[tok*8];
        #pragma unroll
        for (int j = 0; j < 4; j++) {
            float base = acc[i2][j];
            __nv_bfloat16 hb[8];
            #pragma unroll
            for (int m = 0; m < 8; m++)
                hb[m] = __float2bfloat16(base * pr[m]);
            size_t off = (size_t)tok*PMc + (tp + j*16)*8;
            *(uint4*)(dh + off) = *(uint4*)hb;
        }
    }
}

// ---------------- pass A (HMMA): kv[f][d] = sum_i kf[i][f] v[i][d] ----------
__global__ __launch_bounds__(256, 2) void passA_mma_k()
{
    extern __shared__ char sm[];
    u32 sb = smem_u32(sm);
    const u32 KF = 0, VH = 34816, VL = 53248;
    int bhc = blockIdx.x, fb = blockIdx.y;
    int bh = bhc >> 5, c = bhc & 31;
    int tid = threadIdx.x, lane = tid & 31, warp = tid >> 5;
    int wm = warp >> 1, wn = warp & 1;

    const __nv_bfloat16* kh = g_kf + (size_t)bhc*CHc*PMc + fb*128;
    #pragma unroll
    for (int l = 0; l < 8; l++) {
        int idx = tid + l*256;
        int row = idx >> 4, seg = idx & 15;
        CP_ASYNC16(sb + KF + row*272 + seg*16, kh + (size_t)row*PMc + seg*8);
    }
    CP_COMMIT();
    const float* vb = g_qkv + ((size_t)((bh>>4)*Tc + c*CHc))*(3*Ec) + 2*Ec + (bh&15)*64;
    #pragma unroll
    for (int l = 0; l < 8; l++) {
        int idx = tid + l*256;
        int i = idx >> 4, dd = (idx & 15)*4;
        float4 v = *(const float4*)(vb + (size_t)i*(3*Ec) + dd);
        __nv_bfloat16 h0=__float2bfloat16(v.x), h1=__float2bfloat16(v.y);
        __nv_bfloat16 h2=__float2bfloat16(v.z), h3=__float2bfloat16(v.w);
        u32 off = i*144 + dd*2;
        *(__nv_bfloat162*)(sm + VH + off)     = {h0,h1};
        *(__nv_bfloat162*)(sm + VH + off + 4) = {h2,h3};
        *(__nv_bfloat162*)(sm + VL + off)     = {__float2bfloat16(v.x-__bfloat162float(h0)),
                                                 __float2bfloat16(v.y-__bfloat162float(h1))};
        *(__nv_bfloat162*)(sm + VL + off + 4) = {__float2bfloat16(v.z-__bfloat162float(h2)),
                                                 __float2bfloat16(v.w-__bfloat162float(h3))};
    }
    CP_WAIT0();
    __syncthreads();

    if (tid < 128) {
        float s = 0.f;
        for (int i = 0; i < 128; i++)
            s += __bfloat162float(*(const __nv_bfloat16*)(sm + KF + i*272 + tid*2));
        g_ks[(size_t)bhc*PMc + fb*128 + tid] = s;
    }

    int t_row = (lane & 7) + (((lane >> 4) & 1) << 3);
    int t_colbit = ((lane >> 3) & 1) << 3;

    float acc[2][4][4];
    #pragma unroll
    for (int i = 0; i < 2; i++)
        #pragma unroll
        for (int j = 0; j < 4; j++)
            #pragma unroll
            for (int q = 0; q < 4; q++) acc[i][j][q] = 0.f;

    #pragma unroll
    for (int ks16 = 0; ks16 < 8; ks16++) {
        int krow = ks16*16 + t_row;
        u32 af[2][4], bvh[2][4], bvl[2][4];
        #pragma unroll
        for (int mi = 0; mi < 2; mi++) {
            int fc = wm*32 + mi*16 + t_colbit;
            ldsm4t(af[mi][0], af[mi][1], af[mi][2], af[mi][3],
                   sb + KF + krow*272 + fc*2);
        }
        #pragma unroll
        for (int nj = 0; nj < 2; nj++) {
            int dc = wn*32 + nj*16 + t_colbit;
            u32 addr = sb + VH + krow*144 + dc*2;
            ldsm4t(bvh[nj][0], bvh[nj][1], bvh[nj][2], bvh[nj][3], addr);
            ldsm4t(bvl[nj][0], bvl[nj][1], bvl[nj][2], bvl[nj][3], addr + (VL-VH));
        }
        #pragma unroll
        for (int mi = 0; mi < 2; mi++) {
            #pragma unroll
            for (int ng = 0; ng < 4; ng++) {
                int nj = ng >> 1, sel = ng & 1;
                mma16816(acc[mi][ng], af[mi], bvh[nj][sel], bvh[nj][2+sel]);
                mma16816(acc[mi][ng], af[mi], bvl[nj][sel], bvl[nj][2+sel]);
            }
        }
    }
    float* outp = g_ckv + (size_t)bhc*PMc*Dc + (size_t)fb*128*Dc;
    #pragma unroll
    for (int mi = 0; mi < 2; mi++) {
        #pragma unroll
        for (int ng = 0; ng < 4; ng++) {
            int f = wm*32 + mi*16 + (lane >> 2);
            int d = wn*32 + ng*8 + (lane & 3)*2;
            *(float2*)(outp + (size_t)f*64 + d)     = make_float2(acc[mi][ng][0], acc[mi][ng][1]);
            *(float2*)(outp + (size_t)(f+8)*64 + d) = make_float2(acc[mi][ng][2], acc[mi][ng][3]);
        }
    }
}

// ------- fused prefix: blocks [0,1024) do kv+cvt, [1024,1040) do ks ---------
__global__ void prefix_fused_k()
{
    int blk = blockIdx.x;
    if (blk < 1024) {
        size_t e = ((size_t)blk*256 + threadIdx.x)*4;
        size_t bh = e / (PMc*Dc);
        size_t rem = e % (PMc*Dc);
        float4 acc = make_float4(0.f,0.f,0.f,0.f);
        #pragma unroll
        for (int c = 0; c < NCc; c++) {
            size_t p = (bh*NCc + c)*(size_t)(PMc*Dc) + rem;
            float4 v = *(const float4*)(g_ckv + p);
            __nv_bfloat16 h0=__float2bfloat16(acc.x), h1=__float2bfloat16(acc.y);
            __nv_bfloat16 h2=__float2bfloat16(acc.z), h3=__float2bfloat16(acc.w);
            *(__nv_bfloat162*)(g_ckvh+p)   = {h0,h1};
            *(__nv_bfloat162*)(g_ckvh+p+2) = {h2,h3};
            *(__nv_bfloat162*)(g_ckvl+p)   = {__float2bfloat16(acc.x-__bfloat162float(h0)),
                                              __float2bfloat16(acc.y-__bfloat162float(h1))};
            *(__nv_bfloat162*)(g_ckvl+p+2) = {__float2bfloat16(acc.z-__bfloat162float(h2)),
                                              __float2bfloat16(acc.w-__bfloat162float(h3))};
            acc.x += v.x; acc.y += v.y; acc.z += v.z; acc.w += v.w;
        }
    } else {
        size_t e = ((size_t)(blk - 1024)*256 + threadIdx.x)*4;
        size_t bh = e / PMc;
        size_t rem = e % PMc;
        float4 acc = make_float4(0.f,0.f,0.f,0.f);
        #pragma unroll
        for (int c = 0; c < NCc; c++) {
            size_t p = (bh*NCc + c)*(size_t)PMc + rem;
            float4 v = *(const float4*)(g_ks + p);
            *(float4*)(g_ks + p) = acc;
            acc.x += v.x; acc.y += v.y; acc.z += v.z; acc.w += v.w;
        }
    }
}

// ---------------- scores (HMMA): S = qf kf^T (bf16), mask, rowsum, S@v ------
__global__ __launch_bounds__(256, 2) void scores_mma_k()
{
    extern __shared__ char sm[];
    __shared__ float rowsum[128];
    u32 sb = smem_u32(sm);
    int bhc = blockIdx.x;
    int bh = bhc >> 5, c = bhc & 31;
    int tid = threadIdx.x, lane = tid & 31, warp = tid >> 5;
    int wm = warp >> 1, wn = warp & 1;
    if (tid < 128) rowsum[tid] = 0.f;

    const __nv_bfloat16* qf = g_qf + (size_t)bhc*CHc*PMc;
    const __nv_bfloat16* kf = g_kf + (size_t)bhc*CHc*PMc;

    int r0 = (tid*2) >> 2, s0 = (tid*2) & 3;
    int r1 = (tid*2+1) >> 2, s1 = (tid*2+1) & 3;
    int lr = lane & 7;
    int a_row = lr + (((lane >> 3) & 1) << 3);
    int a_col = ((lane >> 4) & 1) << 3;
    int b_row = lr + (((lane >> 4) & 1) << 3);
    int b_col = ((lane >> 3) & 1) << 3;

    float acc[2][8][4];
    #pragma unroll
    for (int i = 0; i < 2; i++)
        #pragma unroll
        for (int j = 0; j < 8; j++)
            #pragma unroll
            for (int q = 0; q < 4; q++) acc[i][j][q] = 0.f;

    auto load_chunk = [&](int ch, int stage) {
        int k0 = ch * 32;
        u32 st = sb + stage * 20480;
        u32 d0 = st + r0*80 + s0*16;
        u32 d1 = st + r1*80 + s1*16;
        CP_ASYNC16(d0,         qf + (size_t)r0*PMc + k0 + s0*8);
        CP_ASYNC16(d1,         qf + (size_t)r1*PMc + k0 + s1*8);
        CP_ASYNC16(d0 + 10240, kf + (size_t)r0*PMc + k0 + s0*8);
        CP_ASYNC16(d1 + 10240, kf + (size_t)r1*PMc + k0 + s1*8);
        CP_COMMIT();
    };

    load_chunk(0, 0);
    for (int ch = 0; ch < 16; ch++) {
        int stage = ch & 1;
        if (ch + 1 < 16) { load_chunk(ch + 1, stage ^ 1); CP_WAIT1(); }
        else             { CP_WAIT0(); }
        __syncthreads();
        u32 st = sb + stage * 20480;
        #pragma unroll
        for (int ks = 0; ks < 2; ks++) {
            u32 af[2][4], bf[4][4];
            #pragma unroll
            for (int mi = 0; mi < 2; mi++) {
                u32 addr = st + ((wm*32 + mi*16 + a_row)*40 + ks*16 + a_col)*2;
                ldsm4(af[mi][0], af[mi][1], af[mi][2], af[mi][3], addr);
            }
            #pragma unroll
            for (int nj = 0; nj < 4; nj++) {
                u32 addr = st + 10240 + ((wn*64 + nj*16 + b_row)*40 + ks*16 + b_col)*2;
                ldsm4(bf[nj][0], bf[nj][1], bf[nj][2], bf[nj][3], addr);
            }
            #pragma unroll
            for (int mi = 0; mi < 2; mi++) {
                #pragma unroll
                for (int ni = 0; ni < 8; ni++) {
                    int nj = ni >> 1, off = (ni & 1) << 1;
                    mma16816(acc[mi][ni], af[mi], bf[nj][off], bf[nj][off+1]);
                }
            }
        }
        __syncthreads();
    }

    #pragma unroll
    for (int mi = 0; mi < 2; mi++) {
        float rs0 = 0.f, rs1 = 0.f;
        int ri0 = wm*32 + mi*16 + (lane >> 2);
        #pragma unroll
        for (int ni = 0; ni < 8; ni++) {
            int cj = wn*64 + ni*8 + (lane & 3)*2;
            float v00 = (cj   <= ri0)   ? acc[mi][ni][0] : 0.f;
            float v01 = (cj+1 <= ri0)   ? acc[mi][ni][1] : 0.f;
            float v10 = (cj   <= ri0+8) ? acc[mi][ni][2] : 0.f;
            float v11 = (cj+1 <= ri0+8) ? acc[mi][ni][3] : 0.f;
            rs0 += v00 + v01; rs1 += v10 + v11;
            __nv_bfloat16 h00=__float2bfloat16(v00), h01=__float2bfloat16(v01);
            __nv_bfloat16 h10=__float2bfloat16(v10), h11=__float2bfloat16(v11);
            u32 o0 = ri0*272 + cj*2, o1 = (ri0+8)*272 + cj*2;
            *(__nv_bfloat162*)(sm + o0)         = {h00,h01};
            *(__nv_bfloat162*)(sm + o1)         = {h10,h11};
            *(__nv_bfloat162*)(sm + 34816 + o0) = {__float2bfloat16(v00-__bfloat162float(h00)),
                                                   __float2bfloat16(v01-__bfloat162float(h01))};
            *(__nv_bfloat162*)(sm + 34816 + o1) = {__float2bfloat16(v10-__bfloat162float(h10)),
                                                   __float2bfloat16(v11-__bfloat162float(h11))};
        }
        rs0 += __shfl_xor_sync(0xffffffffu, rs0, 1);
        rs0 += __shfl_xor_sync(0xffffffffu, rs0, 2);
        rs1 += __shfl_xor_sync(0xffffffffu, rs1, 1);
        rs1 += __shfl_xor_sync(0xffffffffu, rs1, 2);
        if ((lane & 3) == 0) {
            atomicAdd(&rowsum[ri0], rs0);
            atomicAdd(&rowsum[ri0+8], rs1);
        }
    }
    const float* vb = g_qkv + ((size_t)((bh>>4)*Tc + c*CHc))*(3*Ec) + 2*Ec + (bh&15)*64;
    #pragma unroll
    for (int l = 0; l < 8; l++) {
        int idx = tid + l*256;
        int i = idx >> 4, dd = (idx & 15)*4;
        float4 v = *(const float4*)(vb + (size_t)i*(3*Ec) + dd);
        __nv_bfloat16 h0=__float2bfloat16(v.x), h1=__float2bfloat16(v.y);
        __nv_bfloat16 h2=__float2bfloat16(v.z), h3=__float2bfloat16(v.w);
        u32 off = 69632 + i*144 + dd*2;
        *(__nv_bfloat162*)(sm + off)     = {h0,h1};
        *(__nv_bfloat162*)(sm + off + 4) = {h2,h3};
        *(__nv_bfloat162*)(sm + off + (88064-69632))     = {__float2bfloat16(v.x-__bfloat162float(h0)),
                                                            __float2bfloat16(v.y-__bfloat162float(h1))};
        *(__nv_bfloat162*)(sm + off + (88064-69632) + 4) = {__float2bfloat16(v.z-__bfloat162float(h2)),
                                                            __float2bfloat16(v.w-__bfloat162float(h3))};
    }
    __syncthreads();
    if (tid < 128) g_nrm[(size_t)bh*Tc + c*CHc + tid] = rowsum[tid];

    int t_row = (lane & 7) + (((lane >> 4) & 1) << 3);
    int t_colbit = ((lane >> 3) & 1) << 3;
    float acc2[2][4][4];
    #pragma unroll
    for (int i = 0; i < 2; i++)
        #pragma unroll
        for (int j = 0; j < 4; j++)
            #pragma unroll
            for (int q = 0; q < 4; q++) acc2[i][j][q] = 0.f;

    #pragma unroll
    for (int ks16 = 0; ks16 < 8; ks16++) {
        u32 ah2[2][4], al2[2][4], bvh[2][4], bvl[2][4];
        #pragma unroll
        for (int mi = 0; mi < 2; mi++) {
            u32 addr = sb + ((wm*32 + mi*16 + a_row)*136 + ks16*16 + a_col)*2;
            ldsm4(ah2[mi][0], ah2[mi][1], ah2[mi][2], ah2[mi][3], addr);
            ldsm4(al2[mi][0], al2[mi][1], al2[mi][2], al2[mi][3], addr + 34816);
        }
        int krow = ks16*16 + t_row;
        #pragma unroll
        for (int nj = 0; nj < 2; nj++) {
            int dc = wn*32 + nj*16 + t_colbit;
            u32 addr = sb + 69632 + krow*144 + dc*2;
            ldsm4t(bvh[nj][0], bvh[nj][1], bvh[nj][2], bvh[nj][3], addr);
            ldsm4t(bvl[nj][0], bvl[nj][1], bvl[nj][2], bvl[nj][3], addr + (88064-69632));
        }
        #pragma unroll
        for (int mi = 0; mi < 2; mi++) {
            #pragma unroll
            for (int ng = 0; ng < 4; ng++) {
                int nj = ng >> 1, sel = ng & 1;
                mma16816(acc2[mi][ng], ah2[mi], bvh[nj][sel], bvh[nj][2+sel]);
                mma16816(acc2[mi][ng], ah2[mi], bvl[nj][sel], bvl[nj][2+sel]);
                mma16816(acc2[mi][ng], al2[mi], bvh[nj][sel], bvh[nj][2+sel]);
            }
        }
    }
    float* ob = g_o + ((size_t)bh*Tc + c*CHc)*Dc;
    #pragma unroll
    for (int mi = 0; mi < 2; mi++) {
        #pragma unroll
        for (int ng = 0; ng < 4; ng++) {
            int tok = wm*32 + mi*16 + (lane >> 2);
            int d = wn*32 + ng*8 + (lane & 3)*2;
            *(float2*)(ob + (size_t)tok*64 + d)     = make_float2(acc2[mi][ng][0], acc2[mi][ng][1]);
            *(float2*)(ob + (size_t)(tok+8)*64 + d) = make_float2(acc2[mi][ng][2], acc2[mi][ng][3]);
        }
    }
}

// ---------------- hist (HMMA): ctx = qf(bf16) @ kv_state^T(hi/lo) -----------
__global__ __launch_bounds__(256, 2) void hist_mma_k()
{
    extern __shared__ char sm[];
    __shared__ float ks_sm[512];
    __shared__ float nrm_sm[128];
    u32 sb = smem_u32(sm);
    int bhc = blockIdx.x;
    int bh = bhc >> 5, c = bhc & 31;
    int tid = threadIdx.x, lane = tid & 31, warp = tid >> 5;
    int wm = warp >> 1, wn = warp & 1;

    const __nv_bfloat16* qf = g_qf + (size_t)bhc*CHc*PMc;
    const __nv_bfloat16* kvh = g_ckvh + (size_t)bhc*PMc*Dc;
    const __nv_bfloat16* kvl = g_ckvl + (size_t)bhc*PMc*Dc;
    const float* ksb = g_ks + (size_t)bhc*PMc;
    ks_sm[tid] = ksb[tid];
    ks_sm[tid+256] = ksb[tid+256];

    int r0 = (tid*2) >> 2, s0 = (tid*2) & 3;
    int r1 = (tid*2+1) >> 2, s1 = (tid*2+1) & 3;
    int kvr = tid >> 3, kvs = tid & 7;
    int lr = lane & 7;
    int a_row = lr + (((lane >> 3) & 1) << 3);
    int a_col = ((lane >> 4) & 1) << 3;
    int t_row = lr + (((lane >> 4) & 1) << 3);
    int t_colbit = ((lane >> 3) & 1) << 3;

    float acc[2][4][4];
    #pragma unroll
    for (int i = 0; i < 2; i++)
        #pragma unroll
        for (int j = 0; j < 4; j++)
            #pragma unroll
            for (int q = 0; q < 4; q++) acc[i][j][q] = 0.f;
    float nacc = 0.f;

    auto load_chunk = [&](int ch, int stage) {
        int k0 = ch * 32;
        u32 st = sb + stage * 19456;
        u32 d0 = st + r0*80 + s0*16;
        u32 d1 = st + r1*80 + s1*16;
        CP_ASYNC16(d0, qf + (size_t)r0*PMc + k0 + s0*8);
        CP_ASYNC16(d1, qf + (size_t)r1*PMc + k0 + s1*8);
        u32 dk = st + 10240 + kvr*144 + kvs*16;
        CP_ASYNC16(dk,        kvh + (size_t)(k0+kvr)*64 + kvs*8);
        CP_ASYNC16(dk + 4608, kvl + (size_t)(k0+kvr)*64 + kvs*8);
        CP_COMMIT();
    };

    load_chunk(0, 0);
    for (int ch = 0; ch < 16; ch++) {
        int stage = ch & 1;
        if (ch + 1 < 16) { load_chunk(ch + 1, stage ^ 1); CP_WAIT1(); }
        else             { CP_WAIT0(); }
        __syncthreads();
        u32 st = sb + stage * 19456;
        #pragma unroll
        for (int ks16 = 0; ks16 < 2; ks16++) {
            u32 af[2][4], bvh[2][4], bvl[2][4];
            #pragma unroll
            for (int mi = 0; mi < 2; mi++) {
                u32 addr = st + ((wm*32 + mi*16 + a_row)*40 + ks16*16 + a_col)*2;
                ldsm4(af[mi][0], af[mi][1], af[mi][2], af[mi][3], addr);
            }
            int krow = ks16*16 + t_row;
            #pragma unroll
            for (int nj = 0; nj < 2; nj++) {
                int dc = wn*32 + nj*16 + t_colbit;
                u32 addr = st + 10240 + krow*144 + dc*2;
                ldsm4t(bvh[nj][0], bvh[nj][1], bvh[nj][2], bvh[nj][3], addr);
                ldsm4t(bvl[nj][0], bvl[nj][1], bvl[nj][2], bvl[nj][3], addr + 4608);
            }
            #pragma unroll
            for (int mi = 0; mi < 2; mi++) {
                #pragma unroll
                for (int ng = 0; ng < 4; ng++) {
                    int nj = ng >> 1, sel = ng & 1;
                    mma16816(acc[mi][ng], af[mi], bvh[nj][sel], bvh[nj][2+sel]);
                    mma16816(acc[mi][ng], af[mi], bvl[nj][sel], bvl[nj][2+sel]);
                }
            }
        }
        {
            int tt = tid >> 1, fh = (tid & 1)*16;
            const __nv_bfloat16* qs = (const __nv_bfloat16*)(sm + stage*19456 + tt*80);
            #pragma unroll
            for (int f = 0; f < 16; f++) {
                int fl = fh + f;
                nacc += __bfloat162float(qs[fl]) * ks_sm[ch*32 + fl];
            }
        }
        __syncthreads();
    }
    nacc += __shfl_xor_sync(0xffffffffu, nacc, 1);
    if ((tid & 1) == 0) nrm_sm[tid >> 1] = nacc;
    __syncthreads();
    if (tid < 128) {
        float tot = nrm_sm[tid] + g_nrm[(size_t)bh*Tc + c*CHc + tid] + 1e-6f;
        nrm_sm[tid] = 1.f / tot;
    }
    __syncthreads();

    int b_ = bh >> 4, h_ = bh & 15;
    const float* ob = g_o + ((size_t)bh*Tc + c*CHc)*Dc;
    __nv_bfloat16* oh = g_ah + ((size_t)(b_*Tc + c*CHc))*Ec + h_*64;
    __nv_bfloat16* ol = g_al + ((size_t)(b_*Tc + c*CHc))*Ec + h_*64;
    #pragma unroll
    for (int mi = 0; mi < 2; mi++) {
        #pragma unroll
        for (int ng = 0; ng < 4; ng++) {
            int tok = wm*32 + mi*16 + (lane >> 2);
            int d = wn*32 + ng*8 + (lane & 3)*2;
            float inv0 = nrm_sm[tok], inv1 = nrm_sm[tok+8];
            float2 c0 = *(const float2*)(ob + (size_t)tok*64 + d);
            float2 c1 = *(const float2*)(ob + (size_t)(tok+8)*64 + d);
            float v00 = (c0.x + acc[mi][ng][0]) * inv0;
            float v01 = (c0.y + acc[mi][ng][1]) * inv0;
            float v10 = (c1.x + acc[mi][ng][2]) * inv1;
            float v11 = (c1.y + acc[mi][ng][3]) * inv1;
            __nv_bfloat16 h00=__float2bfloat16(v00), h01=__float2bfloat16(v01);
            __nv_bfloat16 h10=__float2bfloat16(v10), h11=__float2bfloat16(v11);
            size_t off0 = (size_t)tok*Ec + d;
            size_t off1 = (size_t)(tok+8)*Ec + d;
            *(__nv_bfloat162*)(oh + off0) = {h00, h01};
            *(__nv_bfloat162*)(oh + off1) = {h10, h11};
            *(__nv_bfloat162*)(ol + off0) = {__float2bfloat16(v00-__bfloat162float(h00)),
                                             __float2bfloat16(v01-__bfloat162float(h01))};
            *(__nv_bfloat162*)(ol + off1) = {__float2bfloat16(v10-__bfloat162float(h10)),
                                             __float2bfloat16(v11-__bfloat162float(h11))};
        }
    }
}

// ---------------- host launcher ---------------------------------------------
extern "C" void kernel_launch(void* const* d_in, const int* in_sizes, int n_in,
                              void* d_out, int out_size)
{
    const float* x        = (const float*)d_in[0];
    const float* qkv_w    = (const float*)d_in[1];
    const float* qkv_b    = (const float*)d_in[2];
    const float* out_w    = (const float*)d_in[3];
    const float* out_b    = (const float*)d_in[4];
    const float* omega    = (const float*)d_in[5];
    const float* poly_w   = (const float*)d_in[6];
    const float* qnodes   = (const float*)d_in[7];
    const float* qweights = (const float*)d_in[8];
    float* out = (float*)d_out;

    float* qkv_ptr = 0;
    cudaGetSymbolAddress((void**)&qkv_ptr, g_qkv);
    __nv_bfloat16 *ah, *al, *wh, *wl, *w2h, *w2l;
    cudaGetSymbolAddress((void**)&ah, g_ah);
    cudaGetSymbolAddress((void**)&al, g_al);
    cudaGetSymbolAddress((void**)&wh, g_wh);
    cudaGetSymbolAddress((void**)&wl, g_wl);
    cudaGetSymbolAddress((void**)&w2h, g_w2h);
    cudaGetSymbolAddress((void**)&w2l, g_w2l);

    cudaFuncSetAttribute(gemm_mma_k, cudaFuncAttributeMaxDynamicSharedMemorySize, 2*S_STAGE);
    cudaFuncSetAttribute(features_k, cudaFuncAttributeMaxDynamicSharedMemorySize, F_SMEM);
    cudaFuncSetAttribute(passA_mma_k, cudaFuncAttributeMaxDynamicSharedMemorySize, 71680);
    cudaFuncSetAttribute(scores_mma_k, cudaFuncAttributeMaxDynamicSharedMemorySize, 106496);
    cudaFuncSetAttribute(hist_mma_k, cudaFuncAttributeMaxDynamicSharedMemorySize, 38912);

    // 1) one combined split for x, qkv_w, out_w
    split3_bf16_k<<<12288, 256>>>(x, qkv_w, out_w);
    // 2) QKV GEMM (HMMA, bf16x3)
    gemm_mma_k<<<dim3(3*Ec/128, (Bc*Tc)/128), 256, 2*S_STAGE>>>(
        ah, al, wh, wl, qkv_b, qkv_ptr, 3*Ec);
    // 3) feature maps -> bf16 (hi only)
    features_k<<<dim3(BHc*NCc, 2), 256, F_SMEM>>>(omega, poly_w, qnodes, qweights);
    // 4) per-chunk kv + ks (HMMA)
    passA_mma_k<<<dim3(BHc*NCc, 4), 256, 71680>>>();
    // 5) fused exclusive prefix
    prefix_fused_k<<<1040, 256>>>();
    // 6) intra-chunk scores + intra context (HMMA)
    scores_mma_k<<<BHc*NCc, 256, 106496>>>();
    // 7) history context + normalize + write bf16 rows (o2rows fused)
    hist_mma_k<<<BHc*NCc, 256, 38912>>>();
    // 8) output projection (HMMA, bf16x3)
    gemm_mma_k<<<dim3(Ec/128, (Bc*Tc)/128), 256, 2*S_STAGE>>>(
        ah, al, w2h, w2l, out_b, out, Ec);
}

// round 14
// speedup vs baseline: 1.0128x; 1.0128x over previous
#include <cuda_runtime.h>
#include <cuda_bf16.h>
#include <math.h>

#define Bc 2
#define Tc 4096
#define Ec 1024
#define Hc 16
#define Dc 64
#define Pc 64
#define PMc 512
#define CHc 128
#define NCc 32
#define BHc 32

typedef unsigned long long u64;
typedef unsigned int u32;

// ---------------- scratch (device globals; no allocations allowed) ----------
__device__ float g_qkv[(size_t)Bc*Tc*3*Ec];
__device__ float g_ckv[(size_t)BHc*NCc*PMc*Dc];
__device__ float g_ks [(size_t)BHc*NCc*PMc];
__device__ float g_o  [(size_t)BHc*Tc*Dc];
__device__ float g_nrm[(size_t)BHc*Tc];
// bf16 features (hi only), [bhc][token 128][feature 512]
__device__ __align__(16) __nv_bfloat16 g_qf[(size_t)BHc*NCc*CHc*PMc];
__device__ __align__(16) __nv_bfloat16 g_kf[(size_t)BHc*NCc*CHc*PMc];
// bf16 hi/lo exclusive kv state, [bhc][f][d]
__device__ __align__(16) __nv_bfloat16 g_ckvh[(size_t)BHc*NCc*PMc*Dc];
__device__ __align__(16) __nv_bfloat16 g_ckvl[(size_t)BHc*NCc*PMc*Dc];
// bf16 split operands for dense GEMMs
__device__ __align__(16) __nv_bfloat16 g_ah[(size_t)Bc*Tc*Ec];
__device__ __align__(16) __nv_bfloat16 g_al[(size_t)Bc*Tc*Ec];
__device__ __align__(16) __nv_bfloat16 g_wh[(size_t)3*Ec*Ec];
__device__ __align__(16) __nv_bfloat16 g_wl[(size_t)3*Ec*Ec];
__device__ __align__(16) __nv_bfloat16 g_w2h[(size_t)Ec*Ec];
__device__ __align__(16) __nv_bfloat16 g_w2l[(size_t)Ec*Ec];

// ================= helpers ===================================================
__device__ __forceinline__ u32 smem_u32(const void* p) {
    u32 a; asm("{ .reg .u64 t; cvta.to.shared.u64 t, %1; cvt.u32.u64 %0, t; }"
               : "=r"(a) : "l"(p));
    return a;
}
#define CP_ASYNC16(dst, src) \
    asm volatile("cp.async.cg.shared.global [%0], [%1], 16;\n" :: "r"(dst), "l"(src))
#define CP_COMMIT() asm volatile("cp.async.commit_group;\n" ::: "memory")
#define CP_WAIT1()  asm volatile("cp.async.wait_group 1;\n" ::: "memory")
#define CP_WAIT0()  asm volatile("cp.async.wait_group 0;\n" ::: "memory")

__device__ __forceinline__ void ldsm4(u32 &r0, u32 &r1, u32 &r2, u32 &r3, u32 a) {
    asm volatile("ldmatrix.sync.aligned.m8n8.x4.shared.b16 {%0,%1,%2,%3}, [%4];\n"
                 : "=r"(r0), "=r"(r1), "=r"(r2), "=r"(r3) : "r"(a));
}
__device__ __forceinline__ void ldsm4t(u32 &r0, u32 &r1, u32 &r2, u32 &r3, u32 a) {
    asm volatile("ldmatrix.sync.aligned.m8n8.x4.trans.shared.b16 {%0,%1,%2,%3}, [%4];\n"
                 : "=r"(r0), "=r"(r1), "=r"(r2), "=r"(r3) : "r"(a));
}
__device__ __forceinline__ void mma16816(float* c, const u32* a, u32 b0, u32 b1) {
    asm volatile(
        "mma.sync.aligned.m16n8k16.row.col.f32.bf16.bf16.f32 "
        "{%0,%1,%2,%3},{%4,%5,%6,%7},{%8,%9},{%0,%1,%2,%3};\n"
        : "+f"(c[0]), "+f"(c[1]), "+f"(c[2]), "+f"(c[3])
        : "r"(a[0]), "r"(a[1]), "r"(a[2]), "r"(a[3]), "r"(b0), "r"(b1));
}

// ======== combined fp32 -> bf16 hi/lo split for x, qkv_w, out_w =============
__global__ void split3_bf16_k(const float* __restrict__ x,
                              const float* __restrict__ qkv_w,
                              const float* __restrict__ out_w)
{
    int blk = blockIdx.x;
    const float* s;
    __nv_bfloat16 *h, *l;
    size_t base;
    if (blk < 8192)       { s = x;     h = g_ah;  l = g_al;  base = (size_t)blk*1024; }
    else if (blk < 11264) { s = qkv_w; h = g_wh;  l = g_wl;  base = (size_t)(blk-8192)*1024; }
    else                  { s = out_w; h = g_w2h; l = g_w2l; base = (size_t)(blk-11264)*1024; }
    size_t i = base + (size_t)threadIdx.x*4;
    float4 v = *(const float4*)(s + i);
    __nv_bfloat16 h0=__float2bfloat16(v.x), h1=__float2bfloat16(v.y);
    __nv_bfloat16 h2=__float2bfloat16(v.z), h3=__float2bfloat16(v.w);
    *(__nv_bfloat162*)(h+i)   = {h0,h1};
    *(__nv_bfloat162*)(h+i+2) = {h2,h3};
    *(__nv_bfloat162*)(l+i)   = {__float2bfloat16(v.x-__bfloat162float(h0)),
                                 __float2bfloat16(v.y-__bfloat162float(h1))};
    *(__nv_bfloat162*)(l+i+2) = {__float2bfloat16(v.z-__bfloat162float(h2)),
                                 __float2bfloat16(v.w-__bfloat162float(h3))};
}

// ================= HMMA GEMM: C[M,N] = A @ W^T + bias (bf16x3 split) ========
#define S_STRIDE 40
#define S_ARR 10240
#define S_STAGE 40960

__global__ __launch_bounds__(256, 2)
void gemm_mma_k(const __nv_bfloat16* __restrict__ Abase_h,
                const __nv_bfloat16* __restrict__ Abase_l,
                const __nv_bfloat16* __restrict__ Wbase_h,
                const __nv_bfloat16* __restrict__ Wbase_l,
                const float* __restrict__ bias, float* __restrict__ C, int N)
{
    extern __shared__ char smem[];
    u32 sb = smem_u32(smem);
    const int K = 1024;
    int tid = threadIdx.x;
    int lane = tid & 31, warp = tid >> 5;
    int wm = warp >> 1, wn = warp & 1;
    int bm = blockIdx.y * 128, bn = blockIdx.x * 128;

    const __nv_bfloat16* Ah = Abase_h + (size_t)bm * K;
    const __nv_bfloat16* Al = Abase_l + (size_t)bm * K;
    const __nv_bfloat16* Wh = Wbase_h + (size_t)bn * K;
    const __nv_bfloat16* Wl = Wbase_l + (size_t)bn * K;

    int r0 = (tid*2) >> 2, s0 = (tid*2) & 3;
    int r1 = (tid*2+1) >> 2, s1 = (tid*2+1) & 3;

    int lr = lane & 7;
    int a_row = lr + (((lane >> 3) & 1) << 3);
    int a_col = ((lane >> 4) & 1) << 3;
    int b_row = lr + (((lane >> 4) & 1) << 3);
    int b_col = ((lane >> 3) & 1) << 3;

    float acc[2][8][4];
    #pragma unroll
    for (int i = 0; i < 2; i++)
        #pragma unroll
        for (int j = 0; j < 8; j++)
            #pragma unroll
            for (int q = 0; q < 4; q++) acc[i][j][q] = 0.f;

    auto load_chunk = [&](int ch, int stage) {
        int k0 = ch * 32;
        u32 st = sb + stage * S_STAGE;
        u32 d0 = st + r0*80 + s0*16;
        u32 d1 = st + r1*80 + s1*16;
        CP_ASYNC16(d0, Ah + (size_t)r0*K + k0 + s0*8);
        CP_ASYNC16(d1, Ah + (size_t)r1*K + k0 + s1*8);
        CP_ASYNC16(d0 + S_ARR, Al + (size_t)r0*K + k0 + s0*8);
        CP_ASYNC16(d1 + S_ARR, Al + (size_t)r1*K + k0 + s1*8);
        CP_ASYNC16(d0 + 2*S_ARR, Wh + (size_t)r0*K + k0 + s0*8);
        CP_ASYNC16(d1 + 2*S_ARR, Wh + (size_t)r1*K + k0 + s1*8);
        CP_ASYNC16(d0 + 3*S_ARR, Wl + (size_t)r0*K + k0 + s0*8);
        CP_ASYNC16(d1 + 3*S_ARR, Wl + (size_t)r1*K + k0 + s1*8);
        CP_COMMIT();
    };

    load_chunk(0, 0);

    for (int ch = 0; ch < 32; ch++) {
        int stage = ch & 1;
        if (ch + 1 < 32) { load_chunk(ch + 1, stage ^ 1); CP_WAIT1(); }
        else             { CP_WAIT0(); }
        __syncthreads();

        u32 st = sb + stage * S_STAGE;
        #pragma unroll
        for (int ks = 0; ks < 2; ks++) {
            u32 afh[2][4], afl[2][4], bfh[4][4], bfl[4][4];
            #pragma unroll
            for (int mi = 0; mi < 2; mi++) {
                u32 addr = st + ((wm*32 + mi*16 + a_row)*S_STRIDE + ks*16 + a_col)*2;
                ldsm4(afh[mi][0], afh[mi][1], afh[mi][2], afh[mi][3], addr);
                ldsm4(afl[mi][0], afl[mi][1], afl[mi][2], afl[mi][3], addr + S_ARR);
            }
            #pragma unroll
            for (int nj = 0; nj < 4; nj++) {
                u32 addr = st + 2*S_ARR +
                           ((wn*64 + nj*16 + b_row)*S_STRIDE + ks*16 + b_col)*2;
                ldsm4(bfh[nj][0], bfh[nj][1], bfh[nj][2], bfh[nj][3], addr);
                ldsm4(bfl[nj][0], bfl[nj][1], bfl[nj][2], bfl[nj][3], addr + S_ARR);
            }
            #pragma unroll
            for (int mi = 0; mi < 2; mi++) {
                #pragma unroll
                for (int ni = 0; ni < 8; ni++) {
                    int nj = ni >> 1, off = (ni & 1) << 1;
                    mma16816(acc[mi][ni], afh[mi], bfh[nj][off], bfh[nj][off+1]);
                    mma16816(acc[mi][ni], afh[mi], bfl[nj][off], bfl[nj][off+1]);
                    mma16816(acc[mi][ni], afl[mi], bfh[nj][off], bfh[nj][off+1]);
                }
            }
        }
        __syncthreads();
    }

    #pragma unroll
    for (int mi = 0; mi < 2; mi++) {
        #pragma unroll
        for (int ni = 0; ni < 8; ni++) {
            int m = bm + wm*32 + mi*16 + (lane >> 2);
            int n = bn + wn*64 + ni*8 + (lane & 3)*2;
            float2 o0, o1;
            o0.x = acc[mi][ni][0] + bias[n];
            o0.y = acc[mi][ni][1] + bias[n+1];
            o1.x = acc[mi][ni][2] + bias[n];
            o1.y = acc[mi][ni][3] + bias[n+1];
            *(float2*)(C + (size_t)m*N + n)     = o0;
            *(float2*)(C + (size_t)(m+8)*N + n) = o1;
        }
    }
}

// ---------------- feature map -> bf16 (hi only) [token][feature] ------------
// (round-12 proven version: [token][68] smem layout)
#define F_XS   0
#define F_PS   (128*68)
#define F_OM   (F_PS + 64*68)
#define F_PRF  (F_OM + 512)
#define F_RN   (F_PRF + 1024)
#define F_SMEM ((F_RN + 128)*4)

__global__ __launch_bounds__(256, 3) void features_k(
    const float* __restrict__ omega, const float* __restrict__ poly_w,
    const float* __restrict__ qnodes, const float* __restrict__ qweights)
{
    extern __shared__ float fsm[];
    float* xs  = fsm + F_XS;
    float* ps  = fsm + F_PS;
    float* om  = fsm + F_OM;
    float* prf = fsm + F_PRF;
    float* rn  = fsm + F_RN;
    int bhc = blockIdx.x;
    int isK = blockIdx.y;
    int bh = bhc >> 5, c = bhc & 31;
    int h = bh & 15, b = bh >> 4;
    const float* src = g_qkv + ((size_t)(b*Tc + c*CHc))*(3*Ec) + isK*Ec + h*64;
    __nv_bfloat16* dh = (isK ? g_kf : g_qf) + (size_t)bhc*CHc*PMc;
    int tid = threadIdx.x;
    #pragma unroll
    for (int l = 0; l < 8; l++) {
        int idx = tid + l*256;
        int i = idx >> 4, dd = (idx & 15) << 2;
        float4 v = *(const float4*)(src + (size_t)i*(3*Ec) + dd);
        *(float4*)&xs[i*68 + dd] = v;
    }
    {
        const float* pwp = poly_w + h*4096;
        #pragma unroll
        for (int l = 0; l < 4; l++) {
            int idx = tid + l*256;
            int d = idx >> 4, pc = (idx & 15) << 2;
            *(float4*)&ps[d*68 + pc] = *(const float4*)(pwp + d*64 + pc);
        }
    }
    om[tid]       = omega[h*512 + tid];
    om[tid + 256] = omega[h*512 + tid + 256];
    __syncthreads();
    if (tid < 128) {
        const float* xr = &xs[tid*68];
        float s = 0.f;
        #pragma unroll
        for (int d = 0; d < 64; d++) { float x = xr[d]; s += x*x; }
        rn[tid] = 1.f / fmaxf(sqrtf(s), 1e-12f);
    }
    __syncthreads();
    float s0 = qnodes[0];
    float sq2s = sqrtf(fmaxf(2.f*s0, 0.f));
    float wq = sqrtf(fmaxf(qweights[0], 0.f));
    float prescale = 0.3535533905932738f * wq;
    #pragma unroll
    for (int l = 0; l < 4; l++) {
        int pair = tid + l*256;
        int i = pair >> 3, m = pair & 7;
        const float* xr = &xs[i*68];
        float a = 0.f;
        #pragma unroll
        for (int d = 0; d < 64; d++) a += xr[d] * om[d*8 + m];
        float e = fminf(fmaxf(a * rn[i] * sq2s - s0, -20.f), 20.f);
        prf[i*8 + m] = expf(e) * prescale;
    }
    __syncthreads();
    int ti = (tid >> 4) << 3, tp = tid & 15;
    float acc[8][4] = {};
    for (int d = 0; d < 64; d++) {
        float a[8];
        #pragma unroll
        for (int x = 0; x < 8; x++) a[x] = xs[(ti+x)*68 + d];
        float b0 = ps[d*68 + tp];
        float b1 = ps[d*68 + tp + 16];
        float b2 = ps[d*68 + tp + 32];
        float b3 = ps[d*68 + tp + 48];
        #pragma unroll
        for (int i2 = 0; i2 < 8; i2++) {
            acc[i2][0] += a[i2]*b0; acc[i2][1] += a[i2]*b1;
            acc[i2][2] += a[i2]*b2; acc[i2][3] += a[i2]*b3;
        }
    }
    #pragma unroll
    for (int i2 = 0; i2 < 8; i2++) {
        float r = rn[ti + i2];
        #pragma unroll
        for (int j = 0; j < 4; j++) {
            float t = acc[i2][j] * r;
            acc[i2][j] = t*t*0.125f;
        }
    }
    #pragma unroll
    for (int i2 = 0; i2 < 8; i2++) {
        int tok = ti + i2;
        const float* pr = &prf[tok*8];
        #pragma unroll
        for (int j = 0; j < 4; j++) {
            float base = acc[i2][j];
            __nv_bfloat16 hb[8];
            #pragma unroll
            for (int m = 0; m < 8; m++)
                hb[m] = __float2bfloat16(base * pr[m]);
            size_t off = (size_t)tok*PMc + (tp + j*16)*8;
            *(uint4*)(dh + off) = *(uint4*)hb;
        }
    }
}

// ---------------- pass A (HMMA): kv[f][d] = sum_i kf[i][f] v[i][d] ----------
__global__ __launch_bounds__(256, 2) void passA_mma_k()
{
    extern __shared__ char sm[];
    u32 sb = smem_u32(sm);
    const u32 KF = 0, VH = 34816, VL = 53248;
    int bhc = blockIdx.x, fb = blockIdx.y;
    int bh = bhc >> 5, c = bhc & 31;
    int tid = threadIdx.x, lane = tid & 31, warp = tid >> 5;
    int wm = warp >> 1, wn = warp & 1;

    const __nv_bfloat16* kh = g_kf + (size_t)bhc*CHc*PMc + fb*128;
    #pragma unroll
    for (int l = 0; l < 8; l++) {
        int idx = tid + l*256;
        int row = idx >> 4, seg = idx & 15;
        CP_ASYNC16(sb + KF + row*272 + seg*16, kh + (size_t)row*PMc + seg*8);
    }
    CP_COMMIT();
    const float* vb = g_qkv + ((size_t)((bh>>4)*Tc + c*CHc))*(3*Ec) + 2*Ec + (bh&15)*64;
    #pragma unroll
    for (int l = 0; l < 8; l++) {
        int idx = tid + l*256;
        int i = idx >> 4, dd = (idx & 15)*4;
        float4 v = *(const float4*)(vb + (size_t)i*(3*Ec) + dd);
        __nv_bfloat16 h0=__float2bfloat16(v.x), h1=__float2bfloat16(v.y);
        __nv_bfloat16 h2=__float2bfloat16(v.z), h3=__float2bfloat16(v.w);
        u32 off = i*144 + dd*2;
        *(__nv_bfloat162*)(sm + VH + off)     = {h0,h1};
        *(__nv_bfloat162*)(sm + VH + off + 4) = {h2,h3};
        *(__nv_bfloat162*)(sm + VL + off)     = {__float2bfloat16(v.x-__bfloat162float(h0)),
                                                 __float2bfloat16(v.y-__bfloat162float(h1))};
        *(__nv_bfloat162*)(sm + VL + off + 4) = {__float2bfloat16(v.z-__bfloat162float(h2)),
                                                 __float2bfloat16(v.w-__bfloat162float(h3))};
    }
    CP_WAIT0();
    __syncthreads();

    if (tid < 128) {
        float s = 0.f;
        for (int i = 0; i < 128; i++)
            s += __bfloat162float(*(const __nv_bfloat16*)(sm + KF + i*272 + tid*2));
        g_ks[(size_t)bhc*PMc + fb*128 + tid] = s;
    }

    int t_row = (lane & 7) + (((lane >> 4) & 1) << 3);
    int t_colbit = ((lane >> 3) & 1) << 3;

    float acc[2][4][4];
    #pragma unroll
    for (int i = 0; i < 2; i++)
        #pragma unroll
        for (int j = 0; j < 4; j++)
            #pragma unroll
            for (int q = 0; q < 4; q++) acc[i][j][q] = 0.f;

    #pragma unroll
    for (int ks16 = 0; ks16 < 8; ks16++) {
        int krow = ks16*16 + t_row;
        u32 af[2][4], bvh[2][4], bvl[2][4];
        #pragma unroll
        for (int mi = 0; mi < 2; mi++) {
            int fc = wm*32 + mi*16 + t_colbit;
            ldsm4t(af[mi][0], af[mi][1], af[mi][2], af[mi][3],
                   sb + KF + krow*272 + fc*2);
        }
        #pragma unroll
        for (int nj = 0; nj < 2; nj++) {
            int dc = wn*32 + nj*16 + t_colbit;
            u32 addr = sb + VH + krow*144 + dc*2;
            ldsm4t(bvh[nj][0], bvh[nj][1], bvh[nj][2], bvh[nj][3], addr);
            ldsm4t(bvl[nj][0], bvl[nj][1], bvl[nj][2], bvl[nj][3], addr + (VL-VH));
        }
        #pragma unroll
        for (int mi = 0; mi < 2; mi++) {
            #pragma unroll
            for (int ng = 0; ng < 4; ng++) {
                int nj = ng >> 1, sel = ng & 1;
                mma16816(acc[mi][ng], af[mi], bvh[nj][sel], bvh[nj][2+sel]);
                mma16816(acc[mi][ng], af[mi], bvl[nj][sel], bvl[nj][2+sel]);
            }
        }
    }
    float* outp = g_ckv + (size_t)bhc*PMc*Dc + (size_t)fb*128*Dc;
    #pragma unroll
    for (int mi = 0; mi < 2; mi++) {
        #pragma unroll
        for (int ng = 0; ng < 4; ng++) {
            int f = wm*32 + mi*16 + (lane >> 2);
            int d = wn*32 + ng*8 + (lane & 3)*2;
            *(float2*)(outp + (size_t)f*64 + d)     = make_float2(acc[mi][ng][0], acc[mi][ng][1]);
            *(float2*)(outp + (size_t)(f+8)*64 + d) = make_float2(acc[mi][ng][2], acc[mi][ng][3]);
        }
    }
}

// ------- fused prefix: blocks [0,1024) do kv+cvt, [1024,1040) do ks ---------
__global__ void prefix_fused_k()
{
    int blk = blockIdx.x;
    if (blk < 1024) {
        size_t e = ((size_t)blk*256 + threadIdx.x)*4;
        size_t bh = e / (PMc*Dc);
        size_t rem = e % (PMc*Dc);
        float4 acc = make_float4(0.f,0.f,0.f,0.f);
        #pragma unroll
        for (int c = 0; c < NCc; c++) {
            size_t p = (bh*NCc + c)*(size_t)(PMc*Dc) + rem;
            float4 v = *(const float4*)(g_ckv + p);
            __nv_bfloat16 h0=__float2bfloat16(acc.x), h1=__float2bfloat16(acc.y);
            __nv_bfloat16 h2=__float2bfloat16(acc.z), h3=__float2bfloat16(acc.w);
            *(__nv_bfloat162*)(g_ckvh+p)   = {h0,h1};
            *(__nv_bfloat162*)(g_ckvh+p+2) = {h2,h3};
            *(__nv_bfloat162*)(g_ckvl+p)   = {__float2bfloat16(acc.x-__bfloat162float(h0)),
                                              __float2bfloat16(acc.y-__bfloat162float(h1))};
            *(__nv_bfloat162*)(g_ckvl+p+2) = {__float2bfloat16(acc.z-__bfloat162float(h2)),
                                              __float2bfloat16(acc.w-__bfloat162float(h3))};
            acc.x += v.x; acc.y += v.y; acc.z += v.z; acc.w += v.w;
        }
    } else {
        size_t e = ((size_t)(blk - 1024)*256 + threadIdx.x)*4;
        size_t bh = e / PMc;
        size_t rem = e % PMc;
        float4 acc = make_float4(0.f,0.f,0.f,0.f);
        #pragma unroll
        for (int c = 0; c < NCc; c++) {
            size_t p = (bh*NCc + c)*(size_t)PMc + rem;
            float4 v = *(const float4*)(g_ks + p);
            *(float4*)(g_ks + p) = acc;
            acc.x += v.x; acc.y += v.y; acc.z += v.z; acc.w += v.w;
        }
    }
}

// ---------------- scores (HMMA): S = qf kf^T (bf16), mask, rowsum, S@v ------
__global__ __launch_bounds__(256, 2) void scores_mma_k()
{
    extern __shared__ char sm[];
    __shared__ float rowsum[128];
    u32 sb = smem_u32(sm);
    int bhc = blockIdx.x;
    int bh = bhc >> 5, c = bhc & 31;
    int tid = threadIdx.x, lane = tid & 31, warp = tid >> 5;
    int wm = warp >> 1, wn = warp & 1;
    if (tid < 128) rowsum[tid] = 0.f;

    const __nv_bfloat16* qf = g_qf + (size_t)bhc*CHc*PMc;
    const __nv_bfloat16* kf = g_kf + (size_t)bhc*CHc*PMc;

    int r0 = (tid*2) >> 2, s0 = (tid*2) & 3;
    int r1 = (tid*2+1) >> 2, s1 = (tid*2+1) & 3;
    int lr = lane & 7;
    int a_row = lr + (((lane >> 3) & 1) << 3);
    int a_col = ((lane >> 4) & 1) << 3;
    int b_row = lr + (((lane >> 4) & 1) << 3);
    int b_col = ((lane >> 3) & 1) << 3;

    float acc[2][8][4];
    #pragma unroll
    for (int i = 0; i < 2; i++)
        #pragma unroll
        for (int j = 0; j < 8; j++)
            #pragma unroll
            for (int q = 0; q < 4; q++) acc[i][j][q] = 0.f;

    auto load_chunk = [&](int ch, int stage) {
        int k0 = ch * 32;
        u32 st = sb + stage * 20480;
        u32 d0 = st + r0*80 + s0*16;
        u32 d1 = st + r1*80 + s1*16;
        CP_ASYNC16(d0,         qf + (size_t)r0*PMc + k0 + s0*8);
        CP_ASYNC16(d1,         qf + (size_t)r1*PMc + k0 + s1*8);
        CP_ASYNC16(d0 + 10240, kf + (size_t)r0*PMc + k0 + s0*8);
        CP_ASYNC16(d1 + 10240, kf + (size_t)r1*PMc + k0 + s1*8);
        CP_COMMIT();
    };

    load_chunk(0, 0);
    for (int ch = 0; ch < 16; ch++) {
        int stage = ch & 1;
        if (ch + 1 < 16) { load_chunk(ch + 1, stage ^ 1); CP_WAIT1(); }
        else             { CP_WAIT0(); }
        __syncthreads();
        u32 st = sb + stage * 20480;
        #pragma unroll
        for (int ks = 0; ks < 2; ks++) {
            u32 af[2][4], bf[4][4];
            #pragma unroll
            for (int mi = 0; mi < 2; mi++) {
                u32 addr = st + ((wm*32 + mi*16 + a_row)*40 + ks*16 + a_col)*2;
                ldsm4(af[mi][0], af[mi][1], af[mi][2], af[mi][3], addr);
            }
            #pragma unroll
            for (int nj = 0; nj < 4; nj++) {
                u32 addr = st + 10240 + ((wn*64 + nj*16 + b_row)*40 + ks*16 + b_col)*2;
                ldsm4(bf[nj][0], bf[nj][1], bf[nj][2], bf[nj][3], addr);
            }
            #pragma unroll
            for (int mi = 0; mi < 2; mi++) {
                #pragma unroll
                for (int ni = 0; ni < 8; ni++) {
                    int nj = ni >> 1, off = (ni & 1) << 1;
                    mma16816(acc[mi][ni], af[mi], bf[nj][off], bf[nj][off+1]);
                }
            }
        }
        __syncthreads();
    }

    #pragma unroll
    for (int mi = 0; mi < 2; mi++) {
        float rs0 = 0.f, rs1 = 0.f;
        int ri0 = wm*32 + mi*16 + (lane >> 2);
        #pragma unroll
        for (int ni = 0; ni < 8; ni++) {
            int cj = wn*64 + ni*8 + (lane & 3)*2;
            float v00 = (cj   <= ri0)   ? acc[mi][ni][0] : 0.f;
            float v01 = (cj+1 <= ri0)   ? acc[mi][ni][1] : 0.f;
            float v10 = (cj   <= ri0+8) ? acc[mi][ni][2] : 0.f;
            float v11 = (cj+1 <= ri0+8) ? acc[mi][ni][3] : 0.f;
            rs0 += v00 + v01; rs1 += v10 + v11;
            __nv_bfloat16 h00=__float2bfloat16(v00), h01=__float2bfloat16(v01);
            __nv_bfloat16 h10=__float2bfloat16(v10), h11=__float2bfloat16(v11);
            u32 o0 = ri0*272 + cj*2, o1 = (ri0+8)*272 + cj*2;
            *(__nv_bfloat162*)(sm + o0)         = {h00,h01};
            *(__nv_bfloat162*)(sm + o1)         = {h10,h11};
            *(__nv_bfloat162*)(sm + 34816 + o0) = {__float2bfloat16(v00-__bfloat162float(h00)),
                                                   __float2bfloat16(v01-__bfloat162float(h01))};
            *(__nv_bfloat162*)(sm + 34816 + o1) = {__float2bfloat16(v10-__bfloat162float(h10)),
                                                   __float2bfloat16(v11-__bfloat162float(h11))};
        }
        rs0 += __shfl_xor_sync(0xffffffffu, rs0, 1);
        rs0 += __shfl_xor_sync(0xffffffffu, rs0, 2);
        rs1 += __shfl_xor_sync(0xffffffffu, rs1, 1);
        rs1 += __shfl_xor_sync(0xffffffffu, rs1, 2);
        if ((lane & 3) == 0) {
            atomicAdd(&rowsum[ri0], rs0);
            atomicAdd(&rowsum[ri0+8], rs1);
        }
    }
    const float* vb = g_qkv + ((size_t)((bh>>4)*Tc + c*CHc))*(3*Ec) + 2*Ec + (bh&15)*64;
    #pragma unroll
    for (int l = 0; l < 8; l++) {
        int idx = tid + l*256;
        int i = idx >> 4, dd = (idx & 15)*4;
        float4 v = *(const float4*)(vb + (size_t)i*(3*Ec) + dd);
        __nv_bfloat16 h0=__float2bfloat16(v.x), h1=__float2bfloat16(v.y);
        __nv_bfloat16 h2=__float2bfloat16(v.z), h3=__float2bfloat16(v.w);
        u32 off = 69632 + i*144 + dd*2;
        *(__nv_bfloat162*)(sm + off)     = {h0,h1};
        *(__nv_bfloat162*)(sm + off + 4) = {h2,h3};
        *(__nv_bfloat162*)(sm + off + (88064-69632))     = {__float2bfloat16(v.x-__bfloat162float(h0)),
                                                            __float2bfloat16(v.y-__bfloat162float(h1))};
        *(__nv_bfloat162*)(sm + off + (88064-69632) + 4) = {__float2bfloat16(v.z-__bfloat162float(h2)),
                                                            __float2bfloat16(v.w-__bfloat162float(h3))};
    }
    __syncthreads();
    if (tid < 128) g_nrm[(size_t)bh*Tc + c*CHc + tid] = rowsum[tid];

    int t_row = (lane & 7) + (((lane >> 4) & 1) << 3);
    int t_colbit = ((lane >> 3) & 1) << 3;
    float acc2[2][4][4];
    #pragma unroll
    for (int i = 0; i < 2; i++)
        #pragma unroll
        for (int j = 0; j < 4; j++)
            #pragma unroll
            for (int q = 0; q < 4; q++) acc2[i][j][q] = 0.f;

    #pragma unroll
    for (int ks16 = 0; ks16 < 8; ks16++) {
        u32 ah2[2][4], al2[2][4], bvh[2][4], bvl[2][4];
        #pragma unroll
        for (int mi = 0; mi < 2; mi++) {
            u32 addr = sb + ((wm*32 + mi*16 + a_row)*136 + ks16*16 + a_col)*2;
            ldsm4(ah2[mi][0], ah2[mi][1], ah2[mi][2], ah2[mi][3], addr);
            ldsm4(al2[mi][0], al2[mi][1], al2[mi][2], al2[mi][3], addr + 34816);
        }
        int krow = ks16*16 + t_row;
        #pragma unroll
        for (int nj = 0; nj < 2; nj++) {
            int dc = wn*32 + nj*16 + t_colbit;
            u32 addr = sb + 69632 + krow*144 + dc*2;
            ldsm4t(bvh[nj][0], bvh[nj][1], bvh[nj][2], bvh[nj][3], addr);
            ldsm4t(bvl[nj][0], bvl[nj][1], bvl[nj][2], bvl[nj][3], addr + (88064-69632));
        }
        #pragma unroll
        for (int mi = 0; mi < 2; mi++) {
            #pragma unroll
            for (int ng = 0; ng < 4; ng++) {
                int nj = ng >> 1, sel = ng & 1;
                mma16816(acc2[mi][ng], ah2[mi], bvh[nj][sel], bvh[nj][2+sel]);
                mma16816(acc2[mi][ng], ah2[mi], bvl[nj][sel], bvl[nj][2+sel]);
                mma16816(acc2[mi][ng], al2[mi], bvh[nj][sel], bvh[nj][2+sel]);
            }
        }
    }
    float* ob = g_o + ((size_t)bh*Tc + c*CHc)*Dc;
    #pragma unroll
    for (int mi = 0; mi < 2; mi++) {
        #pragma unroll
        for (int ng = 0; ng < 4; ng++) {
            int tok = wm*32 + mi*16 + (lane >> 2);
            int d = wn*32 + ng*8 + (lane & 3)*2;
            *(float2*)(ob + (size_t)tok*64 + d)     = make_float2(acc2[mi][ng][0], acc2[mi][ng][1]);
            *(float2*)(ob + (size_t)(tok+8)*64 + d) = make_float2(acc2[mi][ng][2], acc2[mi][ng][3]);
        }
    }
}

// ---------------- hist (HMMA): ctx = qf(bf16) @ kv_state^T(hi/lo) -----------
__global__ __launch_bounds__(256, 2) void hist_mma_k()
{
    extern __shared__ char sm[];
    __shared__ float ks_sm[512];
    __shared__ float nrm_sm[128];
    u32 sb = smem_u32(sm);
    int bhc = blockIdx.x;
    int bh = bhc >> 5, c = bhc & 31;
    int tid = threadIdx.x, lane = tid & 31, warp = tid >> 5;
    int wm = warp >> 1, wn = warp & 1;

    const __nv_bfloat16* qf = g_qf + (size_t)bhc*CHc*PMc;
    const __nv_bfloat16* kvh = g_ckvh + (size_t)bhc*PMc*Dc;
    const __nv_bfloat16* kvl = g_ckvl + (size_t)bhc*PMc*Dc;
    const float* ksb = g_ks + (size_t)bhc*PMc;
    ks_sm[tid] = ksb[tid];
    ks_sm[tid+256] = ksb[tid+256];

    int r0 = (tid*2) >> 2, s0 = (tid*2) & 3;
    int r1 = (tid*2+1) >> 2, s1 = (tid*2+1) & 3;
    int kvr = tid >> 3, kvs = tid & 7;
    int lr = lane & 7;
    int a_row = lr + (((lane >> 3) & 1) << 3);
    int a_col = ((lane >> 4) & 1) << 3;
    int t_row = lr + (((lane >> 4) & 1) << 3);
    int t_colbit = ((lane >> 3) & 1) << 3;

    float acc[2][4][4];
    #pragma unroll
    for (int i = 0; i < 2; i++)
        #pragma unroll
        for (int j = 0; j < 4; j++)
            #pragma unroll
            for (int q = 0; q < 4; q++) acc[i][j][q] = 0.f;
    float nacc = 0.f;

    auto load_chunk = [&](int ch, int stage) {
        int k0 = ch * 32;
        u32 st = sb + stage * 19456;
        u32 d0 = st + r0*80 + s0*16;
        u32 d1 = st + r1*80 + s1*16;
        CP_ASYNC16(d0, qf + (size_t)r0*PMc + k0 + s0*8);
        CP_ASYNC16(d1, qf + (size_t)r1*PMc + k0 + s1*8);
        u32 dk = st + 10240 + kvr*144 + kvs*16;
        CP_ASYNC16(dk,        kvh + (size_t)(k0+kvr)*64 + kvs*8);
        CP_ASYNC16(dk + 4608, kvl + (size_t)(k0+kvr)*64 + kvs*8);
        CP_COMMIT();
    };

    load_chunk(0, 0);
    for (int ch = 0; ch < 16; ch++) {
        int stage = ch & 1;
        if (ch + 1 < 16) { load_chunk(ch + 1, stage ^ 1); CP_WAIT1(); }
        else             { CP_WAIT0(); }
        __syncthreads();
        u32 st = sb + stage * 19456;
        #pragma unroll
        for (int ks16 = 0; ks16 < 2; ks16++) {
            u32 af[2][4], bvh[2][4], bvl[2][4];
            #pragma unroll
            for (int mi = 0; mi < 2; mi++) {
                u32 addr = st + ((wm*32 + mi*16 + a_row)*40 + ks16*16 + a_col)*2;
                ldsm4(af[mi][0], af[mi][1], af[mi][2], af[mi][3], addr);
            }
            int krow = ks16*16 + t_row;
            #pragma unroll
            for (int nj = 0; nj < 2; nj++) {
                int dc = wn*32 + nj*16 + t_colbit;
                u32 addr = st + 10240 + krow*144 + dc*2;
                ldsm4t(bvh[nj][0], bvh[nj][1], bvh[nj][2], bvh[nj][3], addr);
                ldsm4t(bvl[nj][0], bvl[nj][1], bvl[nj][2], bvl[nj][3], addr + 4608);
            }
            #pragma unroll
            for (int mi = 0; mi < 2; mi++) {
                #pragma unroll
                for (int ng = 0; ng < 4; ng++) {
                    int nj = ng >> 1, sel = ng & 1;
                    mma16816(acc[mi][ng], af[mi], bvh[nj][sel], bvh[nj][2+sel]);
                    mma16816(acc[mi][ng], af[mi], bvl[nj][sel], bvl[nj][2+sel]);
                }
            }
        }
        {
            int tt = tid >> 1, fh = (tid & 1)*16;
            const __nv_bfloat16* qs = (const __nv_bfloat16*)(sm + stage*19456 + tt*80);
            #pragma unroll
            for (int f = 0; f < 16; f++) {
                int fl = fh + f;
                nacc += __bfloat162float(qs[fl]) * ks_sm[ch*32 + fl];
            }
        }
        __syncthreads();
    }
    nacc += __shfl_xor_sync(0xffffffffu, nacc, 1);
    if ((tid & 1) == 0) nrm_sm[tid >> 1] = nacc;
    __syncthreads();
    if (tid < 128) {
        float tot = nrm_sm[tid] + g_nrm[(size_t)bh*Tc + c*CHc + tid] + 1e-6f;
        nrm_sm[tid] = 1.f / tot;
    }
    __syncthreads();

    int b_ = bh >> 4, h_ = bh & 15;
    const float* ob = g_o + ((size_t)bh*Tc + c*CHc)*Dc;
    __nv_bfloat16* oh = g_ah + ((size_t)(b_*Tc + c*CHc))*Ec + h_*64;
    __nv_bfloat16* ol = g_al + ((size_t)(b_*Tc + c*CHc))*Ec + h_*64;
    #pragma unroll
    for (int mi = 0; mi < 2; mi++) {
        #pragma unroll
        for (int ng = 0; ng < 4; ng++) {
            int tok = wm*32 + mi*16 + (lane >> 2);
            int d = wn*32 + ng*8 + (lane & 3)*2;
            float inv0 = nrm_sm[tok], inv1 = nrm_sm[tok+8];
            float2 c0 = *(const float2*)(ob + (size_t)tok*64 + d);
            float2 c1 = *(const float2*)(ob + (size_t)(tok+8)*64 + d);
            float v00 = (c0.x + acc[mi][ng][0]) * inv0;
            float v01 = (c0.y + acc[mi][ng][1]) * inv0;
            float v10 = (c1.x + acc[mi][ng][2]) * inv1;
            float v11 = (c1.y + acc[mi][ng][3]) * inv1;
            __nv_bfloat16 h00=__float2bfloat16(v00), h01=__float2bfloat16(v01);
            __nv_bfloat16 h10=__float2bfloat16(v10), h11=__float2bfloat16(v11);
            size_t off0 = (size_t)tok*Ec + d;
            size_t off1 = (size_t)(tok+8)*Ec + d;
            *(__nv_bfloat162*)(oh + off0) = {h00, h01};
            *(__nv_bfloat162*)(oh + off1) = {h10, h11};
            *(__nv_bfloat162*)(ol + off0) = {__float2bfloat16(v00-__bfloat162float(h00)),
                                             __float2bfloat16(v01-__bfloat162float(h01))};
            *(__nv_bfloat162*)(ol + off1) = {__float2bfloat16(v10-__bfloat162float(h10)),
                                             __float2bfloat16(v11-__bfloat162float(h11))};
        }
    }
}

// ---------------- host launcher ---------------------------------------------
extern "C" void kernel_launch(void* const* d_in, const int* in_sizes, int n_in,
                              void* d_out, int out_size)
{
    const float* x        = (const float*)d_in[0];
    const float* qkv_w    = (const float*)d_in[1];
    const float* qkv_b    = (const float*)d_in[2];
    const float* out_w    = (const float*)d_in[3];
    const float* out_b    = (const float*)d_in[4];
    const float* omega    = (const float*)d_in[5];
    const float* poly_w   = (const float*)d_in[6];
    const float* qnodes   = (const float*)d_in[7];
    const float* qweights = (const float*)d_in[8];
    float* out = (float*)d_out;

    float* qkv_ptr = 0;
    cudaGetSymbolAddress((void**)&qkv_ptr, g_qkv);
    __nv_bfloat16 *ah, *al, *wh, *wl, *w2h, *w2l;
    cudaGetSymbolAddress((void**)&ah, g_ah);
    cudaGetSymbolAddress((void**)&al, g_al);
    cudaGetSymbolAddress((void**)&wh, g_wh);
    cudaGetSymbolAddress((void**)&wl, g_wl);
    cudaGetSymbolAddress((void**)&w2h, g_w2h);
    cudaGetSymbolAddress((void**)&w2l, g_w2l);

    cudaFuncSetAttribute(gemm_mma_k, cudaFuncAttributeMaxDynamicSharedMemorySize, 2*S_STAGE);
    cudaFuncSetAttribute(features_k, cudaFuncAttributeMaxDynamicSharedMemorySize, F_SMEM);
    cudaFuncSetAttribute(passA_mma_k, cudaFuncAttributeMaxDynamicSharedMemorySize, 71680);
    cudaFuncSetAttribute(scores_mma_k, cudaFuncAttributeMaxDynamicSharedMemorySize, 106496);
    cudaFuncSetAttribute(hist_mma_k, cudaFuncAttributeMaxDynamicSharedMemorySize, 38912);

    // 1) one combined split for x, qkv_w, out_w
    split3_bf16_k<<<12288, 256>>>(x, qkv_w, out_w);
    // 2) QKV GEMM (HMMA, bf16x3)
    gemm_mma_k<<<dim3(3*Ec/128, (Bc*Tc)/128), 256, 2*S_STAGE>>>(
        ah, al, wh, wl, qkv_b, qkv_ptr, 3*Ec);
    // 3) feature maps -> bf16 (hi only)
    features_k<<<dim3(BHc*NCc, 2), 256, F_SMEM>>>(omega, poly_w, qnodes, qweights);
    // 4) per-chunk kv + ks (HMMA)
    passA_mma_k<<<dim3(BHc*NCc, 4), 256, 71680>>>();
    // 5) fused exclusive prefix
    prefix_fused_k<<<1040, 256>>>();
    // 6) intra-chunk scores + intra context (HMMA)
    scores_mma_k<<<BHc*NCc, 256, 106496>>>();
    // 7) history context + normalize + write bf16 rows (o2rows fused)
    hist_mma_k<<<BHc*NCc, 256, 38912>>>();
    // 8) output projection (HMMA, bf16x3)
    gemm_mma_k<<<dim3(Ec/128, (Bc*Tc)/128), 256, 2*S_STAGE>>>(
        ah, al, w2h, w2l, out_b, out, Ec);
}

// round 15
// speedup vs baseline: 1.0171x; 1.0042x over previous
#include <cuda_runtime.h>
#include <cuda_bf16.h>
#include <math.h>

#define Bc 2
#define Tc 4096
#define Ec 1024
#define Hc 16
#define Dc 64
#define Pc 64
#define PMc 512
#define CHc 128
#define NCc 32
#define BHc 32

typedef unsigned long long u64;
typedef unsigned int u32;

// ---------------- scratch (device globals; no allocations allowed) ----------
__device__ float g_qkv[(size_t)Bc*Tc*3*Ec];
__device__ float g_ckv[(size_t)BHc*NCc*PMc*Dc];
__device__ float g_ks [(size_t)BHc*NCc*PMc];
__device__ float g_o  [(size_t)BHc*Tc*Dc];
__device__ float g_nrm[(size_t)BHc*Tc];
// bf16 features (hi only), [bhc][token 128][feature 512]
__device__ __align__(16) __nv_bfloat16 g_qf[(size_t)BHc*NCc*CHc*PMc];
__device__ __align__(16) __nv_bfloat16 g_kf[(size_t)BHc*NCc*CHc*PMc];
// bf16 hi/lo exclusive kv state, [bhc][f][d]
__device__ __align__(16) __nv_bfloat16 g_ckvh[(size_t)BHc*NCc*PMc*Dc];
__device__ __align__(16) __nv_bfloat16 g_ckvl[(size_t)BHc*NCc*PMc*Dc];
// bf16 split operands for dense GEMMs
__device__ __align__(16) __nv_bfloat16 g_ah[(size_t)Bc*Tc*Ec];
__device__ __align__(16) __nv_bfloat16 g_al[(size_t)Bc*Tc*Ec];
__device__ __align__(16) __nv_bfloat16 g_wh[(size_t)3*Ec*Ec];
__device__ __align__(16) __nv_bfloat16 g_wl[(size_t)3*Ec*Ec];
__device__ __align__(16) __nv_bfloat16 g_w2h[(size_t)Ec*Ec];
__device__ __align__(16) __nv_bfloat16 g_w2l[(size_t)Ec*Ec];

// ================= helpers ===================================================
__device__ __forceinline__ u32 smem_u32(const void* p) {
    u32 a; asm("{ .reg .u64 t; cvta.to.shared.u64 t, %1; cvt.u32.u64 %0, t; }"
               : "=r"(a) : "l"(p));
    return a;
}
#define CP_ASYNC16(dst, src) \
    asm volatile("cp.async.cg.shared.global [%0], [%1], 16;\n" :: "r"(dst), "l"(src))
#define CP_COMMIT() asm volatile("cp.async.commit_group;\n" ::: "memory")
#define CP_WAIT1()  asm volatile("cp.async.wait_group 1;\n" ::: "memory")
#define CP_WAIT0()  asm volatile("cp.async.wait_group 0;\n" ::: "memory")

__device__ __forceinline__ void ldsm4(u32 &r0, u32 &r1, u32 &r2, u32 &r3, u32 a) {
    asm volatile("ldmatrix.sync.aligned.m8n8.x4.shared.b16 {%0,%1,%2,%3}, [%4];\n"
                 : "=r"(r0), "=r"(r1), "=r"(r2), "=r"(r3) : "r"(a));
}
__device__ __forceinline__ void ldsm4t(u32 &r0, u32 &r1, u32 &r2, u32 &r3, u32 a) {
    asm volatile("ldmatrix.sync.aligned.m8n8.x4.trans.shared.b16 {%0,%1,%2,%3}, [%4];\n"
                 : "=r"(r0), "=r"(r1), "=r"(r2), "=r"(r3) : "r"(a));
}
__device__ __forceinline__ void mma16816(float* c, const u32* a, u32 b0, u32 b1) {
    asm volatile(
        "mma.sync.aligned.m16n8k16.row.col.f32.bf16.bf16.f32 "
        "{%0,%1,%2,%3},{%4,%5,%6,%7},{%8,%9},{%0,%1,%2,%3};\n"
        : "+f"(c[0]), "+f"(c[1]), "+f"(c[2]), "+f"(c[3])
        : "r"(a[0]), "r"(a[1]), "r"(a[2]), "r"(a[3]), "r"(b0), "r"(b1));
}

// ======== combined fp32 -> bf16 hi/lo split for x, qkv_w, out_w =============
__global__ void split3_bf16_k(const float* __restrict__ x,
                              const float* __restrict__ qkv_w,
                              const float* __restrict__ out_w)
{
    int blk = blockIdx.x;
    const float* s;
    __nv_bfloat16 *h, *l;
    size_t base;
    if (blk < 8192)       { s = x;     h = g_ah;  l = g_al;  base = (size_t)blk*1024; }
    else if (blk < 11264) { s = qkv_w; h = g_wh;  l = g_wl;  base = (size_t)(blk-8192)*1024; }
    else                  { s = out_w; h = g_w2h; l = g_w2l; base = (size_t)(blk-11264)*1024; }
    size_t i = base + (size_t)threadIdx.x*4;
    float4 v = *(const float4*)(s + i);
    __nv_bfloat16 h0=__float2bfloat16(v.x), h1=__float2bfloat16(v.y);
    __nv_bfloat16 h2=__float2bfloat16(v.z), h3=__float2bfloat16(v.w);
    *(__nv_bfloat162*)(h+i)   = {h0,h1};
    *(__nv_bfloat162*)(h+i+2) = {h2,h3};
    *(__nv_bfloat162*)(l+i)   = {__float2bfloat16(v.x-__bfloat162float(h0)),
                                 __float2bfloat16(v.y-__bfloat162float(h1))};
    *(__nv_bfloat162*)(l+i+2) = {__float2bfloat16(v.z-__bfloat162float(h2)),
                                 __float2bfloat16(v.w-__bfloat162float(h3))};
}

// ================= HMMA GEMM: C[M,N] = A @ W^T + bias (bf16x3 split) ========
#define S_STRIDE 40
#define S_ARR 10240
#define S_STAGE 40960

__global__ __launch_bounds__(256, 2)
void gemm_mma_k(const __nv_bfloat16* __restrict__ Abase_h,
                const __nv_bfloat16* __restrict__ Abase_l,
                const __nv_bfloat16* __restrict__ Wbase_h,
                const __nv_bfloat16* __restrict__ Wbase_l,
                const float* __restrict__ bias, float* __restrict__ C, int N)
{
    extern __shared__ char smem[];
    u32 sb = smem_u32(smem);
    const int K = 1024;
    int tid = threadIdx.x;
    int lane = tid & 31, warp = tid >> 5;
    int wm = warp >> 1, wn = warp & 1;
    int bm = blockIdx.y * 128, bn = blockIdx.x * 128;

    const __nv_bfloat16* Ah = Abase_h + (size_t)bm * K;
    const __nv_bfloat16* Al = Abase_l + (size_t)bm * K;
    const __nv_bfloat16* Wh = Wbase_h + (size_t)bn * K;
    const __nv_bfloat16* Wl = Wbase_l + (size_t)bn * K;

    int r0 = (tid*2) >> 2, s0 = (tid*2) & 3;
    int r1 = (tid*2+1) >> 2, s1 = (tid*2+1) & 3;

    int lr = lane & 7;
    int a_row = lr + (((lane >> 3) & 1) << 3);
    int a_col = ((lane >> 4) & 1) << 3;
    int b_row = lr + (((lane >> 4) & 1) << 3);
    int b_col = ((lane >> 3) & 1) << 3;

    float acc[2][8][4];
    #pragma unroll
    for (int i = 0; i < 2; i++)
        #pragma unroll
        for (int j = 0; j < 8; j++)
            #pragma unroll
            for (int q = 0; q < 4; q++) acc[i][j][q] = 0.f;

    auto load_chunk = [&](int ch, int stage) {
        int k0 = ch * 32;
        u32 st = sb + stage * S_STAGE;
        u32 d0 = st + r0*80 + s0*16;
        u32 d1 = st + r1*80 + s1*16;
        CP_ASYNC16(d0, Ah + (size_t)r0*K + k0 + s0*8);
        CP_ASYNC16(d1, Ah + (size_t)r1*K + k0 + s1*8);
        CP_ASYNC16(d0 + S_ARR, Al + (size_t)r0*K + k0 + s0*8);
        CP_ASYNC16(d1 + S_ARR, Al + (size_t)r1*K + k0 + s1*8);
        CP_ASYNC16(d0 + 2*S_ARR, Wh + (size_t)r0*K + k0 + s0*8);
        CP_ASYNC16(d1 + 2*S_ARR, Wh + (size_t)r1*K + k0 + s1*8);
        CP_ASYNC16(d0 + 3*S_ARR, Wl + (size_t)r0*K + k0 + s0*8);
        CP_ASYNC16(d1 + 3*S_ARR, Wl + (size_t)r1*K + k0 + s1*8);
        CP_COMMIT();
    };

    load_chunk(0, 0);

    for (int ch = 0; ch < 32; ch++) {
        int stage = ch & 1;
        if (ch + 1 < 32) { load_chunk(ch + 1, stage ^ 1); CP_WAIT1(); }
        else             { CP_WAIT0(); }
        __syncthreads();

        u32 st = sb + stage * S_STAGE;
        #pragma unroll
        for (int ks = 0; ks < 2; ks++) {
            u32 afh[2][4], afl[2][4], bfh[4][4], bfl[4][4];
            #pragma unroll
            for (int mi = 0; mi < 2; mi++) {
                u32 addr = st + ((wm*32 + mi*16 + a_row)*S_STRIDE + ks*16 + a_col)*2;
                ldsm4(afh[mi][0], afh[mi][1], afh[mi][2], afh[mi][3], addr);
                ldsm4(afl[mi][0], afl[mi][1], afl[mi][2], afl[mi][3], addr + S_ARR);
            }
            #pragma unroll
            for (int nj = 0; nj < 4; nj++) {
                u32 addr = st + 2*S_ARR +
                           ((wn*64 + nj*16 + b_row)*S_STRIDE + ks*16 + b_col)*2;
                ldsm4(bfh[nj][0], bfh[nj][1], bfh[nj][2], bfh[nj][3], addr);
                ldsm4(bfl[nj][0], bfl[nj][1], bfl[nj][2], bfl[nj][3], addr + S_ARR);
            }
            #pragma unroll
            for (int mi = 0; mi < 2; mi++) {
                #pragma unroll
                for (int ni = 0; ni < 8; ni++) {
                    int nj = ni >> 1, off = (ni & 1) << 1;
                    mma16816(acc[mi][ni], afh[mi], bfh[nj][off], bfh[nj][off+1]);
                    mma16816(acc[mi][ni], afh[mi], bfl[nj][off], bfl[nj][off+1]);
                    mma16816(acc[mi][ni], afl[mi], bfh[nj][off], bfh[nj][off+1]);
                }
            }
        }
        __syncthreads();
    }

    #pragma unroll
    for (int mi = 0; mi < 2; mi++) {
        #pragma unroll
        for (int ni = 0; ni < 8; ni++) {
            int m = bm + wm*32 + mi*16 + (lane >> 2);
            int n = bn + wn*64 + ni*8 + (lane & 3)*2;
            float2 o0, o1;
            o0.x = acc[mi][ni][0] + bias[n];
            o0.y = acc[mi][ni][1] + bias[n+1];
            o1.x = acc[mi][ni][2] + bias[n];
            o1.y = acc[mi][ni][3] + bias[n+1];
            *(float2*)(C + (size_t)m*N + n)     = o0;
            *(float2*)(C + (size_t)(m+8)*N + n) = o1;
        }
    }
}

// ---------------- feature map -> bf16 (hi only) [token][feature] ------------
#define F_XS   0
#define F_PS   (128*68)
#define F_OM   (F_PS + 64*68)
#define F_PRF  (F_OM + 512)
#define F_RN   (F_PRF + 1024)
#define F_SMEM ((F_RN + 128)*4)

__global__ __launch_bounds__(256, 3) void features_k(
    const float* __restrict__ omega, const float* __restrict__ poly_w,
    const float* __restrict__ qnodes, const float* __restrict__ qweights)
{
    extern __shared__ float fsm[];
    float* xs  = fsm + F_XS;
    float* ps  = fsm + F_PS;
    float* om  = fsm + F_OM;
    float* prf = fsm + F_PRF;
    float* rn  = fsm + F_RN;
    int bhc = blockIdx.x;
    int isK = blockIdx.y;
    int bh = bhc >> 5, c = bhc & 31;
    int h = bh & 15, b = bh >> 4;
    const float* src = g_qkv + ((size_t)(b*Tc + c*CHc))*(3*Ec) + isK*Ec + h*64;
    __nv_bfloat16* dh = (isK ? g_kf : g_qf) + (size_t)bhc*CHc*PMc;
    int tid = threadIdx.x;
    #pragma unroll
    for (int l = 0; l < 8; l++) {
        int idx = tid + l*256;
        int i = idx >> 4, dd = (idx & 15) << 2;
        float4 v = *(const float4*)(src + (size_t)i*(3*Ec) + dd);
        *(float4*)&xs[i*68 + dd] = v;
    }
    {
        const float* pwp = poly_w + h*4096;
        #pragma unroll
        for (int l = 0; l < 4; l++) {
            int idx = tid + l*256;
            int d = idx >> 4, pc = (idx & 15) << 2;
            *(float4*)&ps[d*68 + pc] = *(const float4*)(pwp + d*64 + pc);
        }
    }
    om[tid]       = omega[h*512 + tid];
    om[tid + 256] = omega[h*512 + tid + 256];
    __syncthreads();
    if (tid < 128) {
        const float* xr = &xs[tid*68];
        float s = 0.f;
        #pragma unroll
        for (int d = 0; d < 64; d++) { float x = xr[d]; s += x*x; }
        rn[tid] = 1.f / fmaxf(sqrtf(s), 1e-12f);
    }
    __syncthreads();
    float s0 = qnodes[0];
    float sq2s = sqrtf(fmaxf(2.f*s0, 0.f));
    float wq = sqrtf(fmaxf(qweights[0], 0.f));
    float prescale = 0.3535533905932738f * wq;
    #pragma unroll
    for (int l = 0; l < 4; l++) {
        int pair = tid + l*256;
        int i = pair >> 3, m = pair & 7;
        const float* xr = &xs[i*68];
        float a = 0.f;
        #pragma unroll
        for (int d = 0; d < 64; d++) a += xr[d] * om[d*8 + m];
        float e = fminf(fmaxf(a * rn[i] * sq2s - s0, -20.f), 20.f);
        prf[i*8 + m] = expf(e) * prescale;
    }
    __syncthreads();
    int ti = (tid >> 4) << 3, tp = tid & 15;
    float acc[8][4] = {};
    for (int d = 0; d < 64; d++) {
        float a[8];
        #pragma unroll
        for (int x = 0; x < 8; x++) a[x] = xs[(ti+x)*68 + d];
        float b0 = ps[d*68 + tp];
        float b1 = ps[d*68 + tp + 16];
        float b2 = ps[d*68 + tp + 32];
        float b3 = ps[d*68 + tp + 48];
        #pragma unroll
        for (int i2 = 0; i2 < 8; i2++) {
            acc[i2][0] += a[i2]*b0; acc[i2][1] += a[i2]*b1;
            acc[i2][2] += a[i2]*b2; acc[i2][3] += a[i2]*b3;
        }
    }
    #pragma unroll
    for (int i2 = 0; i2 < 8; i2++) {
        float r = rn[ti + i2];
        #pragma unroll
        for (int j = 0; j < 4; j++) {
            float t = acc[i2][j] * r;
            acc[i2][j] = t*t*0.125f;
        }
    }
    #pragma unroll
    for (int i2 = 0; i2 < 8; i2++) {
        int tok = ti + i2;
        const float* pr = &prf[tok*8];
        #pragma unroll
        for (int j = 0; j < 4; j++) {
            float base = acc[i2][j];
            __nv_bfloat16 hb[8];
            #pragma unroll
            for (int m = 0; m < 8; m++)
                hb[m] = __float2bfloat16(base * pr[m]);
            size_t off = (size_t)tok*PMc + (tp + j*16)*8;
            *(uint4*)(dh + off) = *(uint4*)hb;
        }
    }
}

// ---------------- passA body (HMMA): kv[f][d] = sum_i kf[i][f] v[i][d] ------
__device__ __forceinline__ void passA_body(char* sm, u32 sb, int bhc, int fb)
{
    const u32 KF = 0, VH = 34816, VL = 53248;
    int bh = bhc >> 5, c = bhc & 31;
    int tid = threadIdx.x, lane = tid & 31, warp = tid >> 5;
    int wm = warp >> 1, wn = warp & 1;

    const __nv_bfloat16* kh = g_kf + (size_t)bhc*CHc*PMc + fb*128;
    #pragma unroll
    for (int l = 0; l < 8; l++) {
        int idx = tid + l*256;
        int row = idx >> 4, seg = idx & 15;
        CP_ASYNC16(sb + KF + row*272 + seg*16, kh + (size_t)row*PMc + seg*8);
    }
    CP_COMMIT();
    const float* vb = g_qkv + ((size_t)((bh>>4)*Tc + c*CHc))*(3*Ec) + 2*Ec + (bh&15)*64;
    #pragma unroll
    for (int l = 0; l < 8; l++) {
        int idx = tid + l*256;
        int i = idx >> 4, dd = (idx & 15)*4;
        float4 v = *(const float4*)(vb + (size_t)i*(3*Ec) + dd);
        __nv_bfloat16 h0=__float2bfloat16(v.x), h1=__float2bfloat16(v.y);
        __nv_bfloat16 h2=__float2bfloat16(v.z), h3=__float2bfloat16(v.w);
        u32 off = i*144 + dd*2;
        *(__nv_bfloat162*)(sm + VH + off)     = {h0,h1};
        *(__nv_bfloat162*)(sm + VH + off + 4) = {h2,h3};
        *(__nv_bfloat162*)(sm + VL + off)     = {__float2bfloat16(v.x-__bfloat162float(h0)),
                                                 __float2bfloat16(v.y-__bfloat162float(h1))};
        *(__nv_bfloat162*)(sm + VL + off + 4) = {__float2bfloat16(v.z-__bfloat162float(h2)),
                                                 __float2bfloat16(v.w-__bfloat162float(h3))};
    }
    CP_WAIT0();
    __syncthreads();

    if (tid < 128) {
        float s = 0.f;
        for (int i = 0; i < 128; i++)
            s += __bfloat162float(*(const __nv_bfloat16*)(sm + KF + i*272 + tid*2));
        g_ks[(size_t)bhc*PMc + fb*128 + tid] = s;
    }

    int t_row = (lane & 7) + (((lane >> 4) & 1) << 3);
    int t_colbit = ((lane >> 3) & 1) << 3;

    float acc[2][4][4];
    #pragma unroll
    for (int i = 0; i < 2; i++)
        #pragma unroll
        for (int j = 0; j < 4; j++)
            #pragma unroll
            for (int q = 0; q < 4; q++) acc[i][j][q] = 0.f;

    #pragma unroll
    for (int ks16 = 0; ks16 < 8; ks16++) {
        int krow = ks16*16 + t_row;
        u32 af[2][4], bvh[2][4], bvl[2][4];
        #pragma unroll
        for (int mi = 0; mi < 2; mi++) {
            int fc = wm*32 + mi*16 + t_colbit;
            ldsm4t(af[mi][0], af[mi][1], af[mi][2], af[mi][3],
                   sb + KF + krow*272 + fc*2);
        }
        #pragma unroll
        for (int nj = 0; nj < 2; nj++) {
            int dc = wn*32 + nj*16 + t_colbit;
            u32 addr = sb + VH + krow*144 + dc*2;
            ldsm4t(bvh[nj][0], bvh[nj][1], bvh[nj][2], bvh[nj][3], addr);
            ldsm4t(bvl[nj][0], bvl[nj][1], bvl[nj][2], bvl[nj][3], addr + (VL-VH));
        }
        #pragma unroll
        for (int mi = 0; mi < 2; mi++) {
            #pragma unroll
            for (int ng = 0; ng < 4; ng++) {
                int nj = ng >> 1, sel = ng & 1;
                mma16816(acc[mi][ng], af[mi], bvh[nj][sel], bvh[nj][2+sel]);
                mma16816(acc[mi][ng], af[mi], bvl[nj][sel], bvl[nj][2+sel]);
            }
        }
    }
    float* outp = g_ckv + (size_t)bhc*PMc*Dc + (size_t)fb*128*Dc;
    #pragma unroll
    for (int mi = 0; mi < 2; mi++) {
        #pragma unroll
        for (int ng = 0; ng < 4; ng++) {
            int f = wm*32 + mi*16 + (lane >> 2);
            int d = wn*32 + ng*8 + (lane & 3)*2;
            *(float2*)(outp + (size_t)f*64 + d)     = make_float2(acc[mi][ng][0], acc[mi][ng][1]);
            *(float2*)(outp + (size_t)(f+8)*64 + d) = make_float2(acc[mi][ng][2], acc[mi][ng][3]);
        }
    }
}

// ---------------- scores body (HMMA): S = qf kf^T, mask, rowsum, S@v --------
__device__ __forceinline__ void scores_body(char* sm, u32 sb, int bhc, float* rowsum)
{
    int bh = bhc >> 5, c = bhc & 31;
    int tid = threadIdx.x, lane = tid & 31, warp = tid >> 5;
    int wm = warp >> 1, wn = warp & 1;
    if (tid < 128) rowsum[tid] = 0.f;

    const __nv_bfloat16* qf = g_qf + (size_t)bhc*CHc*PMc;
    const __nv_bfloat16* kf = g_kf + (size_t)bhc*CHc*PMc;

    int r0 = (tid*2) >> 2, s0 = (tid*2) & 3;
    int r1 = (tid*2+1) >> 2, s1 = (tid*2+1) & 3;
    int lr = lane & 7;
    int a_row = lr + (((lane >> 3) & 1) << 3);
    int a_col = ((lane >> 4) & 1) << 3;
    int b_row = lr + (((lane >> 4) & 1) << 3);
    int b_col = ((lane >> 3) & 1) << 3;

    float acc[2][8][4];
    #pragma unroll
    for (int i = 0; i < 2; i++)
        #pragma unroll
        for (int j = 0; j < 8; j++)
            #pragma unroll
            for (int q = 0; q < 4; q++) acc[i][j][q] = 0.f;

    auto load_chunk = [&](int ch, int stage) {
        int k0 = ch * 32;
        u32 st = sb + stage * 20480;
        u32 d0 = st + r0*80 + s0*16;
        u32 d1 = st + r1*80 + s1*16;
        CP_ASYNC16(d0,         qf + (size_t)r0*PMc + k0 + s0*8);
        CP_ASYNC16(d1,         qf + (size_t)r1*PMc + k0 + s1*8);
        CP_ASYNC16(d0 + 10240, kf + (size_t)r0*PMc + k0 + s0*8);
        CP_ASYNC16(d1 + 10240, kf + (size_t)r1*PMc + k0 + s1*8);
        CP_COMMIT();
    };

    load_chunk(0, 0);
    for (int ch = 0; ch < 16; ch++) {
        int stage = ch & 1;
        if (ch + 1 < 16) { load_chunk(ch + 1, stage ^ 1); CP_WAIT1(); }
        else             { CP_WAIT0(); }
        __syncthreads();
        u32 st = sb + stage * 20480;
        #pragma unroll
        for (int ks = 0; ks < 2; ks++) {
            u32 af[2][4], bf[4][4];
            #pragma unroll
            for (int mi = 0; mi < 2; mi++) {
                u32 addr = st + ((wm*32 + mi*16 + a_row)*40 + ks*16 + a_col)*2;
                ldsm4(af[mi][0], af[mi][1], af[mi][2], af[mi][3], addr);
            }
            #pragma unroll
            for (int nj = 0; nj < 4; nj++) {
                u32 addr = st + 10240 + ((wn*64 + nj*16 + b_row)*40 + ks*16 + b_col)*2;
                ldsm4(bf[nj][0], bf[nj][1], bf[nj][2], bf[nj][3], addr);
            }
            #pragma unroll
            for (int mi = 0; mi < 2; mi++) {
                #pragma unroll
                for (int ni = 0; ni < 8; ni++) {
                    int nj = ni >> 1, off = (ni & 1) << 1;
                    mma16816(acc[mi][ni], af[mi], bf[nj][off], bf[nj][off+1]);
                }
            }
        }
        __syncthreads();
    }

    #pragma unroll
    for (int mi = 0; mi < 2; mi++) {
        float rs0 = 0.f, rs1 = 0.f;
        int ri0 = wm*32 + mi*16 + (lane >> 2);
        #pragma unroll
        for (int ni = 0; ni < 8; ni++) {
            int cj = wn*64 + ni*8 + (lane & 3)*2;
            float v00 = (cj   <= ri0)   ? acc[mi][ni][0] : 0.f;
            float v01 = (cj+1 <= ri0)   ? acc[mi][ni][1] : 0.f;
            float v10 = (cj   <= ri0+8) ? acc[mi][ni][2] : 0.f;
            float v11 = (cj+1 <= ri0+8) ? acc[mi][ni][3] : 0.f;
            rs0 += v00 + v01; rs1 += v10 + v11;
            __nv_bfloat16 h00=__float2bfloat16(v00), h01=__float2bfloat16(v01);
            __nv_bfloat16 h10=__float2bfloat16(v10), h11=__float2bfloat16(v11);
            u32 o0 = ri0*272 + cj*2, o1 = (ri0+8)*272 + cj*2;
            *(__nv_bfloat162*)(sm + o0)         = {h00,h01};
            *(__nv_bfloat162*)(sm + o1)         = {h10,h11};
            *(__nv_bfloat162*)(sm + 34816 + o0) = {__float2bfloat16(v00-__bfloat162float(h00)),
                                                   __float2bfloat16(v01-__bfloat162float(h01))};
            *(__nv_bfloat162*)(sm + 34816 + o1) = {__float2bfloat16(v10-__bfloat162float(h10)),
                                                   __float2bfloat16(v11-__bfloat162float(h11))};
        }
        rs0 += __shfl_xor_sync(0xffffffffu, rs0, 1);
        rs0 += __shfl_xor_sync(0xffffffffu, rs0, 2);
        rs1 += __shfl_xor_sync(0xffffffffu, rs1, 1);
        rs1 += __shfl_xor_sync(0xffffffffu, rs1, 2);
        if ((lane & 3) == 0) {
            atomicAdd(&rowsum[ri0], rs0);
            atomicAdd(&rowsum[ri0+8], rs1);
        }
    }
    const float* vb = g_qkv + ((size_t)((bh>>4)*Tc + c*CHc))*(3*Ec) + 2*Ec + (bh&15)*64;
    #pragma unroll
    for (int l = 0; l < 8; l++) {
        int idx = tid + l*256;
        int i = idx >> 4, dd = (idx & 15)*4;
        float4 v = *(const float4*)(vb + (size_t)i*(3*Ec) + dd);
        __nv_bfloat16 h0=__float2bfloat16(v.x), h1=__float2bfloat16(v.y);
        __nv_bfloat16 h2=__float2bfloat16(v.z), h3=__float2bfloat16(v.w);
        u32 off = 69632 + i*144 + dd*2;
        *(__nv_bfloat162*)(sm + off)     = {h0,h1};
        *(__nv_bfloat162*)(sm + off + 4) = {h2,h3};
        *(__nv_bfloat162*)(sm + off + (88064-69632))     = {__float2bfloat16(v.x-__bfloat162float(h0)),
                                                            __float2bfloat16(v.y-__bfloat162float(h1))};
        *(__nv_bfloat162*)(sm + off + (88064-69632) + 4) = {__float2bfloat16(v.z-__bfloat162float(h2)),
                                                            __float2bfloat16(v.w-__bfloat162float(h3))};
    }
    __syncthreads();
    if (tid < 128) g_nrm[(size_t)bh*Tc + c*CHc + tid] = rowsum[tid];

    int t_row = (lane & 7) + (((lane >> 4) & 1) << 3);
    int t_colbit = ((lane >> 3) & 1) << 3;
    float acc2[2][4][4];
    #pragma unroll
    for (int i = 0; i < 2; i++)
        #pragma unroll
        for (int j = 0; j < 4; j++)
            #pragma unroll
            for (int q = 0; q < 4; q++) acc2[i][j][q] = 0.f;

    #pragma unroll
    for (int ks16 = 0; ks16 < 8; ks16++) {
        u32 ah2[2][4], al2[2][4], bvh[2][4], bvl[2][4];
        #pragma unroll
        for (int mi = 0; mi < 2; mi++) {
            u32 addr = sb + ((wm*32 + mi*16 + a_row)*136 + ks16*16 + a_col)*2;
            ldsm4(ah2[mi][0], ah2[mi][1], ah2[mi][2], ah2[mi][3], addr);
            ldsm4(al2[mi][0], al2[mi][1], al2[mi][2], al2[mi][3], addr + 34816);
        }
        int krow = ks16*16 + t_row;
        #pragma unroll
        for (int nj = 0; nj < 2; nj++) {
            int dc = wn*32 + nj*16 + t_colbit;
            u32 addr = sb + 69632 + krow*144 + dc*2;
            ldsm4t(bvh[nj][0], bvh[nj][1], bvh[nj][2], bvh[nj][3], addr);
            ldsm4t(bvl[nj][0], bvl[nj][1], bvl[nj][2], bvl[nj][3], addr + (88064-69632));
        }
        #pragma unroll
        for (int mi = 0; mi < 2; mi++) {
            #pragma unroll
            for (int ng = 0; ng < 4; ng++) {
                int nj = ng >> 1, sel = ng & 1;
                mma16816(acc2[mi][ng], ah2[mi], bvh[nj][sel], bvh[nj][2+sel]);
                mma16816(acc2[mi][ng], ah2[mi], bvl[nj][sel], bvl[nj][2+sel]);
                mma16816(acc2[mi][ng], al2[mi], bvh[nj][sel], bvh[nj][2+sel]);
            }
        }
    }
    float* ob = g_o + ((size_t)bh*Tc + c*CHc)*Dc;
    #pragma unroll
    for (int mi = 0; mi < 2; mi++) {
        #pragma unroll
        for (int ng = 0; ng < 4; ng++) {
            int tok = wm*32 + mi*16 + (lane >> 2);
            int d = wn*32 + ng*8 + (lane & 3)*2;
            *(float2*)(ob + (size_t)tok*64 + d)     = make_float2(acc2[mi][ng][0], acc2[mi][ng][1]);
            *(float2*)(ob + (size_t)(tok+8)*64 + d) = make_float2(acc2[mi][ng][2], acc2[mi][ng][3]);
        }
    }
}

// ------- fused passA + scores: blocks [0,1024) scores, [1024,5120) passA ----
__global__ __launch_bounds__(256, 2) void attn_fused_k()
{
    extern __shared__ char sm[];
    __shared__ float rowsum[128];
    u32 sb = smem_u32(sm);
    int blk = blockIdx.x;
    if (blk < 1024) {
        scores_body(sm, sb, blk, rowsum);
    } else {
        int t = blk - 1024;
        passA_body(sm, sb, t >> 2, t & 3);
    }
}

// ------- fused prefix: blocks [0,1024) do kv+cvt, [1024,1040) do ks ---------
__global__ void prefix_fused_k()
{
    int blk = blockIdx.x;
    if (blk < 1024) {
        size_t e = ((size_t)blk*256 + threadIdx.x)*4;
        size_t bh = e / (PMc*Dc);
        size_t rem = e % (PMc*Dc);
        float4 acc = make_float4(0.f,0.f,0.f,0.f);
        #pragma unroll
        for (int c = 0; c < NCc; c++) {
            size_t p = (bh*NCc + c)*(size_t)(PMc*Dc) + rem;
            float4 v = *(const float4*)(g_ckv + p);
            __nv_bfloat16 h0=__float2bfloat16(acc.x), h1=__float2bfloat16(acc.y);
            __nv_bfloat16 h2=__float2bfloat16(acc.z), h3=__float2bfloat16(acc.w);
            *(__nv_bfloat162*)(g_ckvh+p)   = {h0,h1};
            *(__nv_bfloat162*)(g_ckvh+p+2) = {h2,h3};
            *(__nv_bfloat162*)(g_ckvl+p)   = {__float2bfloat16(acc.x-__bfloat162float(h0)),
                                              __float2bfloat16(acc.y-__bfloat162float(h1))};
            *(__nv_bfloat162*)(g_ckvl+p+2) = {__float2bfloat16(acc.z-__bfloat162float(h2)),
                                              __float2bfloat16(acc.w-__bfloat162float(h3))};
            acc.x += v.x; acc.y += v.y; acc.z += v.z; acc.w += v.w;
        }
    } else {
        size_t e = ((size_t)(blk - 1024)*256 + threadIdx.x)*4;
        size_t bh = e / PMc;
        size_t rem = e % PMc;
        float4 acc = make_float4(0.f,0.f,0.f,0.f);
        #pragma unroll
        for (int c = 0; c < NCc; c++) {
            size_t p = (bh*NCc + c)*(size_t)PMc + rem;
            float4 v = *(const float4*)(g_ks + p);
            *(float4*)(g_ks + p) = acc;
            acc.x += v.x; acc.y += v.y; acc.z += v.z; acc.w += v.w;
        }
    }
}

// ---------------- hist (HMMA): ctx = qf(bf16) @ kv_state^T(hi/lo) -----------
__global__ __launch_bounds__(256, 2) void hist_mma_k()
{
    extern __shared__ char sm[];
    __shared__ float ks_sm[512];
    __shared__ float nrm_sm[128];
    u32 sb = smem_u32(sm);
    int bhc = blockIdx.x;
    int bh = bhc >> 5, c = bhc & 31;
    int tid = threadIdx.x, lane = tid & 31, warp = tid >> 5;
    int wm = warp >> 1, wn = warp & 1;

    const __nv_bfloat16* qf = g_qf + (size_t)bhc*CHc*PMc;
    const __nv_bfloat16* kvh = g_ckvh + (size_t)bhc*PMc*Dc;
    const __nv_bfloat16* kvl = g_ckvl + (size_t)bhc*PMc*Dc;
    const float* ksb = g_ks + (size_t)bhc*PMc;
    ks_sm[tid] = ksb[tid];
    ks_sm[tid+256] = ksb[tid+256];

    int r0 = (tid*2) >> 2, s0 = (tid*2) & 3;
    int r1 = (tid*2+1) >> 2, s1 = (tid*2+1) & 3;
    int kvr = tid >> 3, kvs = tid & 7;
    int lr = lane & 7;
    int a_row = lr + (((lane >> 3) & 1) << 3);
    int a_col = ((lane >> 4) & 1) << 3;
    int t_row = lr + (((lane >> 4) & 1) << 3);
    int t_colbit = ((lane >> 3) & 1) << 3;

    float acc[2][4][4];
    #pragma unroll
    for (int i = 0; i < 2; i++)
        #pragma unroll
        for (int j = 0; j < 4; j++)
            #pragma unroll
            for (int q = 0; q < 4; q++) acc[i][j][q] = 0.f;
    float nacc = 0.f;

    auto load_chunk = [&](int ch, int stage) {
        int k0 = ch * 32;
        u32 st = sb + stage * 19456;
        u32 d0 = st + r0*80 + s0*16;
        u32 d1 = st + r1*80 + s1*16;
        CP_ASYNC16(d0, qf + (size_t)r0*PMc + k0 + s0*8);
        CP_ASYNC16(d1, qf + (size_t)r1*PMc + k0 + s1*8);
        u32 dk = st + 10240 + kvr*144 + kvs*16;
        CP_ASYNC16(dk,        kvh + (size_t)(k0+kvr)*64 + kvs*8);
        CP_ASYNC16(dk + 4608, kvl + (size_t)(k0+kvr)*64 + kvs*8);
        CP_COMMIT();
    };

    load_chunk(0, 0);
    for (int ch = 0; ch < 16; ch++) {
        int stage = ch & 1;
        if (ch + 1 < 16) { load_chunk(ch + 1, stage ^ 1); CP_WAIT1(); }
        else             { CP_WAIT0(); }
        __syncthreads();
        u32 st = sb + stage * 19456;
        #pragma unroll
        for (int ks16 = 0; ks16 < 2; ks16++) {
            u32 af[2][4], bvh[2][4], bvl[2][4];
            #pragma unroll
            for (int mi = 0; mi < 2; mi++) {
                u32 addr = st + ((wm*32 + mi*16 + a_row)*40 + ks16*16 + a_col)*2;
                ldsm4(af[mi][0], af[mi][1], af[mi][2], af[mi][3], addr);
            }
            int krow = ks16*16 + t_row;
            #pragma unroll
            for (int nj = 0; nj < 2; nj++) {
                int dc = wn*32 + nj*16 + t_colbit;
                u32 addr = st + 10240 + krow*144 + dc*2;
                ldsm4t(bvh[nj][0], bvh[nj][1], bvh[nj][2], bvh[nj][3], addr);
                ldsm4t(bvl[nj][0], bvl[nj][1], bvl[nj][2], bvl[nj][3], addr + 4608);
            }
            #pragma unroll
            for (int mi = 0; mi < 2; mi++) {
                #pragma unroll
                for (int ng = 0; ng < 4; ng++) {
                    int nj = ng >> 1, sel = ng & 1;
                    mma16816(acc[mi][ng], af[mi], bvh[nj][sel], bvh[nj][2+sel]);
                    mma16816(acc[mi][ng], af[mi], bvl[nj][sel], bvl[nj][2+sel]);
                }
            }
        }
        {
            int tt = tid >> 1, fh = (tid & 1)*16;
            const __nv_bfloat16* qs = (const __nv_bfloat16*)(sm + stage*19456 + tt*80);
            #pragma unroll
            for (int f = 0; f < 16; f++) {
                int fl = fh + f;
                nacc += __bfloat162float(qs[fl]) * ks_sm[ch*32 + fl];
            }
        }
        __syncthreads();
    }
    nacc += __shfl_xor_sync(0xffffffffu, nacc, 1);
    if ((tid & 1) == 0) nrm_sm[tid >> 1] = nacc;
    __syncthreads();
    if (tid < 128) {
        float tot = nrm_sm[tid] + g_nrm[(size_t)bh*Tc + c*CHc + tid] + 1e-6f;
        nrm_sm[tid] = 1.f / tot;
    }
    __syncthreads();

    int b_ = bh >> 4, h_ = bh & 15;
    const float* ob = g_o + ((size_t)bh*Tc + c*CHc)*Dc;
    __nv_bfloat16* oh = g_ah + ((size_t)(b_*Tc + c*CHc))*Ec + h_*64;
    __nv_bfloat16* ol = g_al + ((size_t)(b_*Tc + c*CHc))*Ec + h_*64;
    #pragma unroll
    for (int mi = 0; mi < 2; mi++) {
        #pragma unroll
        for (int ng = 0; ng < 4; ng++) {
            int tok = wm*32 + mi*16 + (lane >> 2);
            int d = wn*32 + ng*8 + (lane & 3)*2;
            float inv0 = nrm_sm[tok], inv1 = nrm_sm[tok+8];
            float2 c0 = *(const float2*)(ob + (size_t)tok*64 + d);
            float2 c1 = *(const float2*)(ob + (size_t)(tok+8)*64 + d);
            float v00 = (c0.x + acc[mi][ng][0]) * inv0;
            float v01 = (c0.y + acc[mi][ng][1]) * inv0;
            float v10 = (c1.x + acc[mi][ng][2]) * inv1;
            float v11 = (c1.y + acc[mi][ng][3]) * inv1;
            __nv_bfloat16 h00=__float2bfloat16(v00), h01=__float2bfloat16(v01);
            __nv_bfloat16 h10=__float2bfloat16(v10), h11=__float2bfloat16(v11);
            size_t off0 = (size_t)tok*Ec + d;
            size_t off1 = (size_t)(tok+8)*Ec + d;
            *(__nv_bfloat162*)(oh + off0) = {h00, h01};
            *(__nv_bfloat162*)(oh + off1) = {h10, h11};
            *(__nv_bfloat162*)(ol + off0) = {__float2bfloat16(v00-__bfloat162float(h00)),
                                             __float2bfloat16(v01-__bfloat162float(h01))};
            *(__nv_bfloat162*)(ol + off1) = {__float2bfloat16(v10-__bfloat162float(h10)),
                                             __float2bfloat16(v11-__bfloat162float(h11))};
        }
    }
}

// ---------------- host launcher ---------------------------------------------
extern "C" void kernel_launch(void* const* d_in, const int* in_sizes, int n_in,
                              void* d_out, int out_size)
{
    const float* x        = (const float*)d_in[0];
    const float* qkv_w    = (const float*)d_in[1];
    const float* qkv_b    = (const float*)d_in[2];
    const float* out_w    = (const float*)d_in[3];
    const float* out_b    = (const float*)d_in[4];
    const float* omega    = (const float*)d_in[5];
    const float* poly_w   = (const float*)d_in[6];
    const float* qnodes   = (const float*)d_in[7];
    const float* qweights = (const float*)d_in[8];
    float* out = (float*)d_out;

    float* qkv_ptr = 0;
    cudaGetSymbolAddress((void**)&qkv_ptr, g_qkv);
    __nv_bfloat16 *ah, *al, *wh, *wl, *w2h, *w2l;
    cudaGetSymbolAddress((void**)&ah, g_ah);
    cudaGetSymbolAddress((void**)&al, g_al);
    cudaGetSymbolAddress((void**)&wh, g_wh);
    cudaGetSymbolAddress((void**)&wl, g_wl);
    cudaGetSymbolAddress((void**)&w2h, g_w2h);
    cudaGetSymbolAddress((void**)&w2l, g_w2l);

    cudaFuncSetAttribute(gemm_mma_k, cudaFuncAttributeMaxDynamicSharedMemorySize, 2*S_STAGE);
    cudaFuncSetAttribute(features_k, cudaFuncAttributeMaxDynamicSharedMemorySize, F_SMEM);
    cudaFuncSetAttribute(attn_fused_k, cudaFuncAttributeMaxDynamicSharedMemorySize, 106496);
    cudaFuncSetAttribute(hist_mma_k, cudaFuncAttributeMaxDynamicSharedMemorySize, 38912);

    // 1) one combined split for x, qkv_w, out_w
    split3_bf16_k<<<12288, 256>>>(x, qkv_w, out_w);
    // 2) QKV GEMM (HMMA, bf16x3)
    gemm_mma_k<<<dim3(3*Ec/128, (Bc*Tc)/128), 256, 2*S_STAGE>>>(
        ah, al, wh, wl, qkv_b, qkv_ptr, 3*Ec);
    // 3) feature maps -> bf16 (hi only)
    features_k<<<dim3(BHc*NCc, 2), 256, F_SMEM>>>(omega, poly_w, qnodes, qweights);
    // 4) fused: scores (blocks 0..1023) + passA (blocks 1024..5119), concurrent
    attn_fused_k<<<5120, 256, 106496>>>();
    // 5) fused exclusive prefix
    prefix_fused_k<<<1040, 256>>>();
    // 6) history context + normalize + write bf16 rows (o2rows fused)
    hist_mma_k<<<BHc*NCc, 256, 38912>>>();
    // 7) output projection (HMMA, bf16x3)
    gemm_mma_k<<<dim3(Ec/128, (Bc*Tc)/128), 256, 2*S_STAGE>>>(
        ah, al, w2h, w2l, out_b, out, Ec);
}

// round 16
// speedup vs baseline: 1.0255x; 1.0083x over previous
#include <cuda_runtime.h>
#include <cuda_bf16.h>
#include <math.h>

#define Bc 2
#define Tc 4096
#define Ec 1024
#define Hc 16
#define Dc 64
#define Pc 64
#define PMc 512
#define CHc 128
#define NCc 32
#define BHc 32

typedef unsigned long long u64;
typedef unsigned int u32;

// ---------------- scratch (device globals; no allocations allowed) ----------
__device__ float g_qkv[(size_t)Bc*Tc*3*Ec];
__device__ float g_ckv[(size_t)BHc*NCc*PMc*Dc];
__device__ float g_ks [(size_t)BHc*NCc*PMc];
__device__ float g_o  [(size_t)BHc*Tc*Dc];
__device__ float g_nrm[(size_t)BHc*Tc];
// bf16 features (hi only), [bhc][token 128][feature 512]
__device__ __align__(16) __nv_bfloat16 g_qf[(size_t)BHc*NCc*CHc*PMc];
__device__ __align__(16) __nv_bfloat16 g_kf[(size_t)BHc*NCc*CHc*PMc];
// bf16 hi/lo exclusive kv state, [bhc][f][d]
__device__ __align__(16) __nv_bfloat16 g_ckvh[(size_t)BHc*NCc*PMc*Dc];
__device__ __align__(16) __nv_bfloat16 g_ckvl[(size_t)BHc*NCc*PMc*Dc];
// bf16 split operands for dense GEMMs
__device__ __align__(16) __nv_bfloat16 g_ah[(size_t)Bc*Tc*Ec];
__device__ __align__(16) __nv_bfloat16 g_al[(size_t)Bc*Tc*Ec];
__device__ __align__(16) __nv_bfloat16 g_wh[(size_t)3*Ec*Ec];
__device__ __align__(16) __nv_bfloat16 g_wl[(size_t)3*Ec*Ec];
__device__ __align__(16) __nv_bfloat16 g_w2h[(size_t)Ec*Ec];
__device__ __align__(16) __nv_bfloat16 g_w2l[(size_t)Ec*Ec];

// ================= helpers ===================================================
__device__ __forceinline__ u32 smem_u32(const void* p) {
    u32 a; asm("{ .reg .u64 t; cvta.to.shared.u64 t, %1; cvt.u32.u64 %0, t; }"
               : "=r"(a) : "l"(p));
    return a;
}
#define CP_ASYNC16(dst, src) \
    asm volatile("cp.async.cg.shared.global [%0], [%1], 16;\n" :: "r"(dst), "l"(src))
#define CP_COMMIT() asm volatile("cp.async.commit_group;\n" ::: "memory")
#define CP_WAIT1()  asm volatile("cp.async.wait_group 1;\n" ::: "memory")
#define CP_WAIT0()  asm volatile("cp.async.wait_group 0;\n" ::: "memory")

__device__ __forceinline__ void ldsm4(u32 &r0, u32 &r1, u32 &r2, u32 &r3, u32 a) {
    asm volatile("ldmatrix.sync.aligned.m8n8.x4.shared.b16 {%0,%1,%2,%3}, [%4];\n"
                 : "=r"(r0), "=r"(r1), "=r"(r2), "=r"(r3) : "r"(a));
}
__device__ __forceinline__ void ldsm4t(u32 &r0, u32 &r1, u32 &r2, u32 &r3, u32 a) {
    asm volatile("ldmatrix.sync.aligned.m8n8.x4.trans.shared.b16 {%0,%1,%2,%3}, [%4];\n"
                 : "=r"(r0), "=r"(r1), "=r"(r2), "=r"(r3) : "r"(a));
}
__device__ __forceinline__ void mma16816(float* c, const u32* a, u32 b0, u32 b1) {
    asm volatile(
        "mma.sync.aligned.m16n8k16.row.col.f32.bf16.bf16.f32 "
        "{%0,%1,%2,%3},{%4,%5,%6,%7},{%8,%9},{%0,%1,%2,%3};\n"
        : "+f"(c[0]), "+f"(c[1]), "+f"(c[2]), "+f"(c[3])
        : "r"(a[0]), "r"(a[1]), "r"(a[2]), "r"(a[3]), "r"(b0), "r"(b1));
}

// ======== combined fp32 -> bf16 hi/lo split for x, qkv_w, out_w =============
__global__ void split3_bf16_k(const float* __restrict__ x,
                              const float* __restrict__ qkv_w,
                              const float* __restrict__ out_w)
{
    int blk = blockIdx.x;
    const float* s;
    __nv_bfloat16 *h, *l;
    size_t base;
    if (blk < 8192)       { s = x;     h = g_ah;  l = g_al;  base = (size_t)blk*1024; }
    else if (blk < 11264) { s = qkv_w; h = g_wh;  l = g_wl;  base = (size_t)(blk-8192)*1024; }
    else                  { s = out_w; h = g_w2h; l = g_w2l; base = (size_t)(blk-11264)*1024; }
    size_t i = base + (size_t)threadIdx.x*4;
    float4 v = *(const float4*)(s + i);
    __nv_bfloat16 h0=__float2bfloat16(v.x), h1=__float2bfloat16(v.y);
    __nv_bfloat16 h2=__float2bfloat16(v.z), h3=__float2bfloat16(v.w);
    *(__nv_bfloat162*)(h+i)   = {h0,h1};
    *(__nv_bfloat162*)(h+i+2) = {h2,h3};
    *(__nv_bfloat162*)(l+i)   = {__float2bfloat16(v.x-__bfloat162float(h0)),
                                 __float2bfloat16(v.y-__bfloat162float(h1))};
    *(__nv_bfloat162*)(l+i+2) = {__float2bfloat16(v.z-__bfloat162float(h2)),
                                 __float2bfloat16(v.w-__bfloat162float(h3))};
}

// ================= HMMA GEMM: C[M,N] = A @ W^T + bias (bf16x3 split) ========
#define S_STRIDE 40
#define S_ARR 10240
#define S_STAGE 40960

__global__ __launch_bounds__(256, 2)
void gemm_mma_k(const __nv_bfloat16* __restrict__ Abase_h,
                const __nv_bfloat16* __restrict__ Abase_l,
                const __nv_bfloat16* __restrict__ Wbase_h,
                const __nv_bfloat16* __restrict__ Wbase_l,
                const float* __restrict__ bias, float* __restrict__ C, int N)
{
    extern __shared__ char smem[];
    u32 sb = smem_u32(smem);
    const int K = 1024;
    int tid = threadIdx.x;
    int lane = tid & 31, warp = tid >> 5;
    int wm = warp >> 1, wn = warp & 1;
    int bm = blockIdx.y * 128, bn = blockIdx.x * 128;

    const __nv_bfloat16* Ah = Abase_h + (size_t)bm * K;
    const __nv_bfloat16* Al = Abase_l + (size_t)bm * K;
    const __nv_bfloat16* Wh = Wbase_h + (size_t)bn * K;
    const __nv_bfloat16* Wl = Wbase_l + (size_t)bn * K;

    int r0 = (tid*2) >> 2, s0 = (tid*2) & 3;
    int r1 = (tid*2+1) >> 2, s1 = (tid*2+1) & 3;

    int lr = lane & 7;
    int a_row = lr + (((lane >> 3) & 1) << 3);
    int a_col = ((lane >> 4) & 1) << 3;
    int b_row = lr + (((lane >> 4) & 1) << 3);
    int b_col = ((lane >> 3) & 1) << 3;

    float acc[2][8][4];
    #pragma unroll
    for (int i = 0; i < 2; i++)
        #pragma unroll
        for (int j = 0; j < 8; j++)
            #pragma unroll
            for (int q = 0; q < 4; q++) acc[i][j][q] = 0.f;

    auto load_chunk = [&](int ch, int stage) {
        int k0 = ch * 32;
        u32 st = sb + stage * S_STAGE;
        u32 d0 = st + r0*80 + s0*16;
        u32 d1 = st + r1*80 + s1*16;
        CP_ASYNC16(d0, Ah + (size_t)r0*K + k0 + s0*8);
        CP_ASYNC16(d1, Ah + (size_t)r1*K + k0 + s1*8);
        CP_ASYNC16(d0 + S_ARR, Al + (size_t)r0*K + k0 + s0*8);
        CP_ASYNC16(d1 + S_ARR, Al + (size_t)r1*K + k0 + s1*8);
        CP_ASYNC16(d0 + 2*S_ARR, Wh + (size_t)r0*K + k0 + s0*8);
        CP_ASYNC16(d1 + 2*S_ARR, Wh + (size_t)r1*K + k0 + s1*8);
        CP_ASYNC16(d0 + 3*S_ARR, Wl + (size_t)r0*K + k0 + s0*8);
        CP_ASYNC16(d1 + 3*S_ARR, Wl + (size_t)r1*K + k0 + s1*8);
        CP_COMMIT();
    };

    load_chunk(0, 0);

    for (int ch = 0; ch < 32; ch++) {
        int stage = ch & 1;
        if (ch + 1 < 32) { load_chunk(ch + 1, stage ^ 1); CP_WAIT1(); }
        else             { CP_WAIT0(); }
        __syncthreads();

        u32 st = sb + stage * S_STAGE;
        #pragma unroll
        for (int ks = 0; ks < 2; ks++) {
            u32 afh[2][4], afl[2][4], bfh[4][4], bfl[4][4];
            #pragma unroll
            for (int mi = 0; mi < 2; mi++) {
                u32 addr = st + ((wm*32 + mi*16 + a_row)*S_STRIDE + ks*16 + a_col)*2;
                ldsm4(afh[mi][0], afh[mi][1], afh[mi][2], afh[mi][3], addr);
                ldsm4(afl[mi][0], afl[mi][1], afl[mi][2], afl[mi][3], addr + S_ARR);
            }
            #pragma unroll
            for (int nj = 0; nj < 4; nj++) {
                u32 addr = st + 2*S_ARR +
                           ((wn*64 + nj*16 + b_row)*S_STRIDE + ks*16 + b_col)*2;
                ldsm4(bfh[nj][0], bfh[nj][1], bfh[nj][2], bfh[nj][3], addr);
                ldsm4(bfl[nj][0], bfl[nj][1], bfl[nj][2], bfl[nj][3], addr + S_ARR);
            }
            #pragma unroll
            for (int mi = 0; mi < 2; mi++) {
                #pragma unroll
                for (int ni = 0; ni < 8; ni++) {
                    int nj = ni >> 1, off = (ni & 1) << 1;
                    mma16816(acc[mi][ni], afh[mi], bfh[nj][off], bfh[nj][off+1]);
                    mma16816(acc[mi][ni], afh[mi], bfl[nj][off], bfl[nj][off+1]);
                    mma16816(acc[mi][ni], afl[mi], bfh[nj][off], bfh[nj][off+1]);
                }
            }
        }
        __syncthreads();
    }

    #pragma unroll
    for (int mi = 0; mi < 2; mi++) {
        #pragma unroll
        for (int ni = 0; ni < 8; ni++) {
            int m = bm + wm*32 + mi*16 + (lane >> 2);
            int n = bn + wn*64 + ni*8 + (lane & 3)*2;
            float2 o0, o1;
            o0.x = acc[mi][ni][0] + bias[n];
            o0.y = acc[mi][ni][1] + bias[n+1];
            o1.x = acc[mi][ni][2] + bias[n];
            o1.y = acc[mi][ni][3] + bias[n+1];
            *(float2*)(C + (size_t)m*N + n)     = o0;
            *(float2*)(C + (size_t)(m+8)*N + n) = o1;
        }
    }
}

// ---------------- feature map -> bf16 (hi only) [token][feature] ------------
#define F_XS   0
#define F_PS   (128*68)
#define F_OM   (F_PS + 64*68)
#define F_PRF  (F_OM + 512)
#define F_RN   (F_PRF + 1024)
#define F_SMEM ((F_RN + 128)*4)

__global__ __launch_bounds__(256, 3) void features_k(
    const float* __restrict__ omega, const float* __restrict__ poly_w,
    const float* __restrict__ qnodes, const float* __restrict__ qweights)
{
    extern __shared__ float fsm[];
    float* xs  = fsm + F_XS;
    float* ps  = fsm + F_PS;
    float* om  = fsm + F_OM;
    float* prf = fsm + F_PRF;
    float* rn  = fsm + F_RN;
    int bhc = blockIdx.x;
    int isK = blockIdx.y;
    int bh = bhc >> 5, c = bhc & 31;
    int h = bh & 15, b = bh >> 4;
    const float* src = g_qkv + ((size_t)(b*Tc + c*CHc))*(3*Ec) + isK*Ec + h*64;
    __nv_bfloat16* dh = (isK ? g_kf : g_qf) + (size_t)bhc*CHc*PMc;
    int tid = threadIdx.x;
    #pragma unroll
    for (int l = 0; l < 8; l++) {
        int idx = tid + l*256;
        int i = idx >> 4, dd = (idx & 15) << 2;
        float4 v = *(const float4*)(src + (size_t)i*(3*Ec) + dd);
        *(float4*)&xs[i*68 + dd] = v;
    }
    {
        const float* pwp = poly_w + h*4096;
        #pragma unroll
        for (int l = 0; l < 4; l++) {
            int idx = tid + l*256;
            int d = idx >> 4, pc = (idx & 15) << 2;
            *(float4*)&ps[d*68 + pc] = *(const float4*)(pwp + d*64 + pc);
        }
    }
    om[tid]       = omega[h*512 + tid];
    om[tid + 256] = omega[h*512 + tid + 256];
    __syncthreads();
    if (tid < 128) {
        const float* xr = &xs[tid*68];
        float s = 0.f;
        #pragma unroll
        for (int d = 0; d < 64; d++) { float x = xr[d]; s += x*x; }
        rn[tid] = 1.f / fmaxf(sqrtf(s), 1e-12f);
    }
    __syncthreads();
    float s0 = qnodes[0];
    float sq2s = sqrtf(fmaxf(2.f*s0, 0.f));
    float wq = sqrtf(fmaxf(qweights[0], 0.f));
    float prescale = 0.3535533905932738f * wq;
    #pragma unroll
    for (int l = 0; l < 4; l++) {
        int pair = tid + l*256;
        int i = pair >> 3, m = pair & 7;
        const float* xr = &xs[i*68];
        float a = 0.f;
        #pragma unroll
        for (int d = 0; d < 64; d++) a += xr[d] * om[d*8 + m];
        float e = fminf(fmaxf(a * rn[i] * sq2s - s0, -20.f), 20.f);
        prf[i*8 + m] = __expf(e) * prescale;
    }
    __syncthreads();
    int ti = (tid >> 4) << 3, tp = tid & 15;
    float acc[8][4] = {};
    for (int d = 0; d < 64; d++) {
        float a[8];
        #pragma unroll
        for (int x = 0; x < 8; x++) a[x] = xs[(ti+x)*68 + d];
        float b0 = ps[d*68 + tp];
        float b1 = ps[d*68 + tp + 16];
        float b2 = ps[d*68 + tp + 32];
        float b3 = ps[d*68 + tp + 48];
        #pragma unroll
        for (int i2 = 0; i2 < 8; i2++) {
            acc[i2][0] += a[i2]*b0; acc[i2][1] += a[i2]*b1;
            acc[i2][2] += a[i2]*b2; acc[i2][3] += a[i2]*b3;
        }
    }
    #pragma unroll
    for (int i2 = 0; i2 < 8; i2++) {
        float r = rn[ti + i2];
        #pragma unroll
        for (int j = 0; j < 4; j++) {
            float t = acc[i2][j] * r;
            acc[i2][j] = t*t*0.125f;
        }
    }
    #pragma unroll
    for (int i2 = 0; i2 < 8; i2++) {
        int tok = ti + i2;
        const float* pr = &prf[tok*8];
        #pragma unroll
        for (int j = 0; j < 4; j++) {
            float base = acc[i2][j];
            __nv_bfloat16 hb[8];
            #pragma unroll
            for (int m = 0; m < 8; m++)
                hb[m] = __float2bfloat16(base * pr[m]);
            size_t off = (size_t)tok*PMc + (tp + j*16)*8;
            *(uint4*)(dh + off) = *(uint4*)hb;
        }
    }
}

// ---------------- passA body (HMMA): kv[f][d] = sum_i kf[i][f] v[i][d] ------
__device__ __forceinline__ void passA_body(char* sm, u32 sb, int bhc, int fb)
{
    const u32 KF = 0, VH = 34816, VL = 53248;
    int bh = bhc >> 5, c = bhc & 31;
    int tid = threadIdx.x, lane = tid & 31, warp = tid >> 5;
    int wm = warp >> 1, wn = warp & 1;

    const __nv_bfloat16* kh = g_kf + (size_t)bhc*CHc*PMc + fb*128;
    #pragma unroll
    for (int l = 0; l < 8; l++) {
        int idx = tid + l*256;
        int row = idx >> 4, seg = idx & 15;
        CP_ASYNC16(sb + KF + row*272 + seg*16, kh + (size_t)row*PMc + seg*8);
    }
    CP_COMMIT();
    const float* vb = g_qkv + ((size_t)((bh>>4)*Tc + c*CHc))*(3*Ec) + 2*Ec + (bh&15)*64;
    #pragma unroll
    for (int l = 0; l < 8; l++) {
        int idx = tid + l*256;
        int i = idx >> 4, dd = (idx & 15)*4;
        float4 v = *(const float4*)(vb + (size_t)i*(3*Ec) + dd);
        __nv_bfloat16 h0=__float2bfloat16(v.x), h1=__float2bfloat16(v.y);
        __nv_bfloat16 h2=__float2bfloat16(v.z), h3=__float2bfloat16(v.w);
        u32 off = i*144 + dd*2;
        *(__nv_bfloat162*)(sm + VH + off)     = {h0,h1};
        *(__nv_bfloat162*)(sm + VH + off + 4) = {h2,h3};
        *(__nv_bfloat162*)(sm + VL + off)     = {__float2bfloat16(v.x-__bfloat162float(h0)),
                                                 __float2bfloat16(v.y-__bfloat162float(h1))};
        *(__nv_bfloat162*)(sm + VL + off + 4) = {__float2bfloat16(v.z-__bfloat162float(h2)),
                                                 __float2bfloat16(v.w-__bfloat162float(h3))};
    }
    CP_WAIT0();
    __syncthreads();

    if (tid < 128) {
        float s = 0.f;
        for (int i = 0; i < 128; i++)
            s += __bfloat162float(*(const __nv_bfloat16*)(sm + KF + i*272 + tid*2));
        g_ks[(size_t)bhc*PMc + fb*128 + tid] = s;
    }

    int t_row = (lane & 7) + (((lane >> 4) & 1) << 3);
    int t_colbit = ((lane >> 3) & 1) << 3;

    float acc[2][4][4];
    #pragma unroll
    for (int i = 0; i < 2; i++)
        #pragma unroll
        for (int j = 0; j < 4; j++)
            #pragma unroll
            for (int q = 0; q < 4; q++) acc[i][j][q] = 0.f;

    #pragma unroll
    for (int ks16 = 0; ks16 < 8; ks16++) {
        int krow = ks16*16 + t_row;
        u32 af[2][4], bvh[2][4], bvl[2][4];
        #pragma unroll
        for (int mi = 0; mi < 2; mi++) {
            int fc = wm*32 + mi*16 + t_colbit;
            ldsm4t(af[mi][0], af[mi][1], af[mi][2], af[mi][3],
                   sb + KF + krow*272 + fc*2);
        }
        #pragma unroll
        for (int nj = 0; nj < 2; nj++) {
            int dc = wn*32 + nj*16 + t_colbit;
            u32 addr = sb + VH + krow*144 + dc*2;
            ldsm4t(bvh[nj][0], bvh[nj][1], bvh[nj][2], bvh[nj][3], addr);
            ldsm4t(bvl[nj][0], bvl[nj][1], bvl[nj][2], bvl[nj][3], addr + (VL-VH));
        }
        #pragma unroll
        for (int mi = 0; mi < 2; mi++) {
            #pragma unroll
            for (int ng = 0; ng < 4; ng++) {
                int nj = ng >> 1, sel = ng & 1;
                mma16816(acc[mi][ng], af[mi], bvh[nj][sel], bvh[nj][2+sel]);
                mma16816(acc[mi][ng], af[mi], bvl[nj][sel], bvl[nj][2+sel]);
            }
        }
    }
    float* outp = g_ckv + (size_t)bhc*PMc*Dc + (size_t)fb*128*Dc;
    #pragma unroll
    for (int mi = 0; mi < 2; mi++) {
        #pragma unroll
        for (int ng = 0; ng < 4; ng++) {
            int f = wm*32 + mi*16 + (lane >> 2);
            int d = wn*32 + ng*8 + (lane & 3)*2;
            *(float2*)(outp + (size_t)f*64 + d)     = make_float2(acc[mi][ng][0], acc[mi][ng][1]);
            *(float2*)(outp + (size_t)(f+8)*64 + d) = make_float2(acc[mi][ng][2], acc[mi][ng][3]);
        }
    }
}

// ---------------- scores body (HMMA): S = qf kf^T, mask, rowsum, S@v --------
__device__ __forceinline__ void scores_body(char* sm, u32 sb, int bhc, float* rowsum)
{
    int bh = bhc >> 5, c = bhc & 31;
    int tid = threadIdx.x, lane = tid & 31, warp = tid >> 5;
    int wm = warp >> 1, wn = warp & 1;
    if (tid < 128) rowsum[tid] = 0.f;

    const __nv_bfloat16* qf = g_qf + (size_t)bhc*CHc*PMc;
    const __nv_bfloat16* kf = g_kf + (size_t)bhc*CHc*PMc;

    int r0 = (tid*2) >> 2, s0 = (tid*2) & 3;
    int r1 = (tid*2+1) >> 2, s1 = (tid*2+1) & 3;
    int lr = lane & 7;
    int a_row = lr + (((lane >> 3) & 1) << 3);
    int a_col = ((lane >> 4) & 1) << 3;
    int b_row = lr + (((lane >> 4) & 1) << 3);
    int b_col = ((lane >> 3) & 1) << 3;

    float acc[2][8][4];
    #pragma unroll
    for (int i = 0; i < 2; i++)
        #pragma unroll
        for (int j = 0; j < 8; j++)
            #pragma unroll
            for (int q = 0; q < 4; q++) acc[i][j][q] = 0.f;

    auto load_chunk = [&](int ch, int stage) {
        int k0 = ch * 32;
        u32 st = sb + stage * 20480;
        u32 d0 = st + r0*80 + s0*16;
        u32 d1 = st + r1*80 + s1*16;
        CP_ASYNC16(d0,         qf + (size_t)r0*PMc + k0 + s0*8);
        CP_ASYNC16(d1,         qf + (size_t)r1*PMc + k0 + s1*8);
        CP_ASYNC16(d0 + 10240, kf + (size_t)r0*PMc + k0 + s0*8);
        CP_ASYNC16(d1 + 10240, kf + (size_t)r1*PMc + k0 + s1*8);
        CP_COMMIT();
    };

    load_chunk(0, 0);
    for (int ch = 0; ch < 16; ch++) {
        int stage = ch & 1;
        if (ch + 1 < 16) { load_chunk(ch + 1, stage ^ 1); CP_WAIT1(); }
        else             { CP_WAIT0(); }
        __syncthreads();
        u32 st = sb + stage * 20480;
        #pragma unroll
        for (int ks = 0; ks < 2; ks++) {
            u32 af[2][4], bf[4][4];
            #pragma unroll
            for (int mi = 0; mi < 2; mi++) {
                u32 addr = st + ((wm*32 + mi*16 + a_row)*40 + ks*16 + a_col)*2;
                ldsm4(af[mi][0], af[mi][1], af[mi][2], af[mi][3], addr);
            }
            #pragma unroll
            for (int nj = 0; nj < 4; nj++) {
                u32 addr = st + 10240 + ((wn*64 + nj*16 + b_row)*40 + ks*16 + b_col)*2;
                ldsm4(bf[nj][0], bf[nj][1], bf[nj][2], bf[nj][3], addr);
            }
            #pragma unroll
            for (int mi = 0; mi < 2; mi++) {
                #pragma unroll
                for (int ni = 0; ni < 8; ni++) {
                    int nj = ni >> 1, off = (ni & 1) << 1;
                    mma16816(acc[mi][ni], af[mi], bf[nj][off], bf[nj][off+1]);
                }
            }
        }
        __syncthreads();
    }

    #pragma unroll
    for (int mi = 0; mi < 2; mi++) {
        float rs0 = 0.f, rs1 = 0.f;
        int ri0 = wm*32 + mi*16 + (lane >> 2);
        #pragma unroll
        for (int ni = 0; ni < 8; ni++) {
            int cj = wn*64 + ni*8 + (lane & 3)*2;
            float v00 = (cj   <= ri0)   ? acc[mi][ni][0] : 0.f;
            float v01 = (cj+1 <= ri0)   ? acc[mi][ni][1] : 0.f;
            float v10 = (cj   <= ri0+8) ? acc[mi][ni][2] : 0.f;
            float v11 = (cj+1 <= ri0+8) ? acc[mi][ni][3] : 0.f;
            rs0 += v00 + v01; rs1 += v10 + v11;
            __nv_bfloat16 h00=__float2bfloat16(v00), h01=__float2bfloat16(v01);
            __nv_bfloat16 h10=__float2bfloat16(v10), h11=__float2bfloat16(v11);
            u32 o0 = ri0*272 + cj*2, o1 = (ri0+8)*272 + cj*2;
            *(__nv_bfloat162*)(sm + o0)         = {h00,h01};
            *(__nv_bfloat162*)(sm + o1)         = {h10,h11};
            *(__nv_bfloat162*)(sm + 34816 + o0) = {__float2bfloat16(v00-__bfloat162float(h00)),
                                                   __float2bfloat16(v01-__bfloat162float(h01))};
            *(__nv_bfloat162*)(sm + 34816 + o1) = {__float2bfloat16(v10-__bfloat162float(h10)),
                                                   __float2bfloat16(v11-__bfloat162float(h11))};
        }
        rs0 += __shfl_xor_sync(0xffffffffu, rs0, 1);
        rs0 += __shfl_xor_sync(0xffffffffu, rs0, 2);
        rs1 += __shfl_xor_sync(0xffffffffu, rs1, 1);
        rs1 += __shfl_xor_sync(0xffffffffu, rs1, 2);
        if ((lane & 3) == 0) {
            atomicAdd(&rowsum[ri0], rs0);
            atomicAdd(&rowsum[ri0+8], rs1);
        }
    }
    const float* vb = g_qkv + ((size_t)((bh>>4)*Tc + c*CHc))*(3*Ec) + 2*Ec + (bh&15)*64;
    #pragma unroll
    for (int l = 0; l < 8; l++) {
        int idx = tid + l*256;
        int i = idx >> 4, dd = (idx & 15)*4;
        float4 v = *(const float4*)(vb + (size_t)i*(3*Ec) + dd);
        __nv_bfloat16 h0=__float2bfloat16(v.x), h1=__float2bfloat16(v.y);
        __nv_bfloat16 h2=__float2bfloat16(v.z), h3=__float2bfloat16(v.w);
        u32 off = 69632 + i*144 + dd*2;
        *(__nv_bfloat162*)(sm + off)     = {h0,h1};
        *(__nv_bfloat162*)(sm + off + 4) = {h2,h3};
        *(__nv_bfloat162*)(sm + off + (88064-69632))     = {__float2bfloat16(v.x-__bfloat162float(h0)),
                                                            __float2bfloat16(v.y-__bfloat162float(h1))};
        *(__nv_bfloat162*)(sm + off + (88064-69632) + 4) = {__float2bfloat16(v.z-__bfloat162float(h2)),
                                                            __float2bfloat16(v.w-__bfloat162float(h3))};
    }
    __syncthreads();
    if (tid < 128) g_nrm[(size_t)bh*Tc + c*CHc + tid] = rowsum[tid];

    int t_row = (lane & 7) + (((lane >> 4) & 1) << 3);
    int t_colbit = ((lane >> 3) & 1) << 3;
    float acc2[2][4][4];
    #pragma unroll
    for (int i = 0; i < 2; i++)
        #pragma unroll
        for (int j = 0; j < 4; j++)
            #pragma unroll
            for (int q = 0; q < 4; q++) acc2[i][j][q] = 0.f;

    #pragma unroll
    for (int ks16 = 0; ks16 < 8; ks16++) {
        u32 ah2[2][4], al2[2][4], bvh[2][4], bvl[2][4];
        #pragma unroll
        for (int mi = 0; mi < 2; mi++) {
            u32 addr = sb + ((wm*32 + mi*16 + a_row)*136 + ks16*16 + a_col)*2;
            ldsm4(ah2[mi][0], ah2[mi][1], ah2[mi][2], ah2[mi][3], addr);
            ldsm4(al2[mi][0], al2[mi][1], al2[mi][2], al2[mi][3], addr + 34816);
        }
        int krow = ks16*16 + t_row;
        #pragma unroll
        for (int nj = 0; nj < 2; nj++) {
            int dc = wn*32 + nj*16 + t_colbit;
            u32 addr = sb + 69632 + krow*144 + dc*2;
            ldsm4t(bvh[nj][0], bvh[nj][1], bvh[nj][2], bvh[nj][3], addr);
            ldsm4t(bvl[nj][0], bvl[nj][1], bvl[nj][2], bvl[nj][3], addr + (88064-69632));
        }
        #pragma unroll
        for (int mi = 0; mi < 2; mi++) {
            #pragma unroll
            for (int ng = 0; ng < 4; ng++) {
                int nj = ng >> 1, sel = ng & 1;
                mma16816(acc2[mi][ng], ah2[mi], bvh[nj][sel], bvh[nj][2+sel]);
                mma16816(acc2[mi][ng], ah2[mi], bvl[nj][sel], bvl[nj][2+sel]);
                mma16816(acc2[mi][ng], al2[mi], bvh[nj][sel], bvh[nj][2+sel]);
            }
        }
    }
    float* ob = g_o + ((size_t)bh*Tc + c*CHc)*Dc;
    #pragma unroll
    for (int mi = 0; mi < 2; mi++) {
        #pragma unroll
        for (int ng = 0; ng < 4; ng++) {
            int tok = wm*32 + mi*16 + (lane >> 2);
            int d = wn*32 + ng*8 + (lane & 3)*2;
            *(float2*)(ob + (size_t)tok*64 + d)     = make_float2(acc2[mi][ng][0], acc2[mi][ng][1]);
            *(float2*)(ob + (size_t)(tok+8)*64 + d) = make_float2(acc2[mi][ng][2], acc2[mi][ng][3]);
        }
    }
}

// ------- fused passA + scores: blocks [0,1024) scores, [1024,5120) passA ----
__global__ __launch_bounds__(256, 2) void attn_fused_k()
{
    extern __shared__ char sm[];
    __shared__ float rowsum[128];
    u32 sb = smem_u32(sm);
    int blk = blockIdx.x;
    if (blk < 1024) {
        scores_body(sm, sb, blk, rowsum);
    } else {
        int t = blk - 1024;
        passA_body(sm, sb, t >> 2, t & 3);
    }
}

// ------- fused prefix: blocks [0,1024) do kv+cvt, [1024,1040) do ks ---------
__global__ void prefix_fused_k()
{
    int blk = blockIdx.x;
    if (blk < 1024) {
        size_t e = ((size_t)blk*256 + threadIdx.x)*4;
        size_t bh = e / (PMc*Dc);
        size_t rem = e % (PMc*Dc);
        float4 acc = make_float4(0.f,0.f,0.f,0.f);
        #pragma unroll
        for (int c = 0; c < NCc; c++) {
            size_t p = (bh*NCc + c)*(size_t)(PMc*Dc) + rem;
            float4 v = *(const float4*)(g_ckv + p);
            __nv_bfloat16 h0=__float2bfloat16(acc.x), h1=__float2bfloat16(acc.y);
            __nv_bfloat16 h2=__float2bfloat16(acc.z), h3=__float2bfloat16(acc.w);
            *(__nv_bfloat162*)(g_ckvh+p)   = {h0,h1};
            *(__nv_bfloat162*)(g_ckvh+p+2) = {h2,h3};
            *(__nv_bfloat162*)(g_ckvl+p)   = {__float2bfloat16(acc.x-__bfloat162float(h0)),
                                              __float2bfloat16(acc.y-__bfloat162float(h1))};
            *(__nv_bfloat162*)(g_ckvl+p+2) = {__float2bfloat16(acc.z-__bfloat162float(h2)),
                                              __float2bfloat16(acc.w-__bfloat162float(h3))};
            acc.x += v.x; acc.y += v.y; acc.z += v.z; acc.w += v.w;
        }
    } else {
        size_t e = ((size_t)(blk - 1024)*256 + threadIdx.x)*4;
        size_t bh = e / PMc;
        size_t rem = e % PMc;
        float4 acc = make_float4(0.f,0.f,0.f,0.f);
        #pragma unroll
        for (int c = 0; c < NCc; c++) {
            size_t p = (bh*NCc + c)*(size_t)PMc + rem;
            float4 v = *(const float4*)(g_ks + p);
            *(float4*)(g_ks + p) = acc;
            acc.x += v.x; acc.y += v.y; acc.z += v.z; acc.w += v.w;
        }
    }
}

// ---------------- hist (HMMA): ctx = qf(bf16) @ kv_state^T(hi/lo) -----------
__global__ __launch_bounds__(256, 3) void hist_mma_k()
{
    extern __shared__ char sm[];
    __shared__ float ks_sm[512];
    __shared__ float nrm_sm[128];
    u32 sb = smem_u32(sm);
    int bhc = blockIdx.x;
    int bh = bhc >> 5, c = bhc & 31;
    int tid = threadIdx.x, lane = tid & 31, warp = tid >> 5;
    int wm = warp >> 1, wn = warp & 1;

    const __nv_bfloat16* qf = g_qf + (size_t)bhc*CHc*PMc;
    const __nv_bfloat16* kvh = g_ckvh + (size_t)bhc*PMc*Dc;
    const __nv_bfloat16* kvl = g_ckvl + (size_t)bhc*PMc*Dc;
    const float* ksb = g_ks + (size_t)bhc*PMc;
    ks_sm[tid] = ksb[tid];
    ks_sm[tid+256] = ksb[tid+256];

    int r0 = (tid*2) >> 2, s0 = (tid*2) & 3;
    int r1 = (tid*2+1) >> 2, s1 = (tid*2+1) & 3;
    int kvr = tid >> 3, kvs = tid & 7;
    int lr = lane & 7;
    int a_row = lr + (((lane >> 3) & 1) << 3);
    int a_col = ((lane >> 4) & 1) << 3;
    int t_row = lr + (((lane >> 4) & 1) << 3);
    int t_colbit = ((lane >> 3) & 1) << 3;

    float acc[2][4][4];
    #pragma unroll
    for (int i = 0; i < 2; i++)
        #pragma unroll
        for (int j = 0; j < 4; j++)
            #pragma unroll
            for (int q = 0; q < 4; q++) acc[i][j][q] = 0.f;
    float nacc = 0.f;

    auto load_chunk = [&](int ch, int stage) {
        int k0 = ch * 32;
        u32 st = sb + stage * 19456;
        u32 d0 = st + r0*80 + s0*16;
        u32 d1 = st + r1*80 + s1*16;
        CP_ASYNC16(d0, qf + (size_t)r0*PMc + k0 + s0*8);
        CP_ASYNC16(d1, qf + (size_t)r1*PMc + k0 + s1*8);
        u32 dk = st + 10240 + kvr*144 + kvs*16;
        CP_ASYNC16(dk,        kvh + (size_t)(k0+kvr)*64 + kvs*8);
        CP_ASYNC16(dk + 4608, kvl + (size_t)(k0+kvr)*64 + kvs*8);
        CP_COMMIT();
    };

    load_chunk(0, 0);
    for (int ch = 0; ch < 16; ch++) {
        int stage = ch & 1;
        if (ch + 1 < 16) { load_chunk(ch + 1, stage ^ 1); CP_WAIT1(); }
        else             { CP_WAIT0(); }
        __syncthreads();
        u32 st = sb + stage * 19456;
        #pragma unroll
        for (int ks16 = 0; ks16 < 2; ks16++) {
            u32 af[2][4], bvh[2][4], bvl[2][4];
            #pragma unroll
            for (int mi = 0; mi < 2; mi++) {
                u32 addr = st + ((wm*32 + mi*16 + a_row)*40 + ks16*16 + a_col)*2;
                ldsm4(af[mi][0], af[mi][1], af[mi][2], af[mi][3], addr);
            }
            int krow = ks16*16 + t_row;
            #pragma unroll
            for (int nj = 0; nj < 2; nj++) {
                int dc = wn*32 + nj*16 + t_colbit;
                u32 addr = st + 10240 + krow*144 + dc*2;
                ldsm4t(bvh[nj][0], bvh[nj][1], bvh[nj][2], bvh[nj][3], addr);
                ldsm4t(bvl[nj][0], bvl[nj][1], bvl[nj][2], bvl[nj][3], addr + 4608);
            }
            #pragma unroll
            for (int mi = 0; mi < 2; mi++) {
                #pragma unroll
                for (int ng = 0; ng < 4; ng++) {
                    int nj = ng >> 1, sel = ng & 1;
                    mma16816(acc[mi][ng], af[mi], bvh[nj][sel], bvh[nj][2+sel]);
                    mma16816(acc[mi][ng], af[mi], bvl[nj][sel], bvl[nj][2+sel]);
                }
            }
        }
        {
            int tt = tid >> 1, fh = (tid & 1)*16;
            const __nv_bfloat16* qs = (const __nv_bfloat16*)(sm + stage*19456 + tt*80);
            #pragma unroll
            for (int f = 0; f < 16; f++) {
                int fl = fh + f;
                nacc += __bfloat162float(qs[fl]) * ks_sm[ch*32 + fl];
            }
        }
        __syncthreads();
    }
    nacc += __shfl_xor_sync(0xffffffffu, nacc, 1);
    if ((tid & 1) == 0) nrm_sm[tid >> 1] = nacc;
    __syncthreads();
    if (tid < 128) {
        float tot = nrm_sm[tid] + g_nrm[(size_t)bh*Tc + c*CHc + tid] + 1e-6f;
        nrm_sm[tid] = 1.f / tot;
    }
    __syncthreads();

    int b_ = bh >> 4, h_ = bh & 15;
    const float* ob = g_o + ((size_t)bh*Tc + c*CHc)*Dc;
    __nv_bfloat16* oh = g_ah + ((size_t)(b_*Tc + c*CHc))*Ec + h_*64;
    __nv_bfloat16* ol = g_al + ((size_t)(b_*Tc + c*CHc))*Ec + h_*64;
    #pragma unroll
    for (int mi = 0; mi < 2; mi++) {
        #pragma unroll
        for (int ng = 0; ng < 4; ng++) {
            int tok = wm*32 + mi*16 + (lane >> 2);
            int d = wn*32 + ng*8 + (lane & 3)*2;
            float inv0 = nrm_sm[tok], inv1 = nrm_sm[tok+8];
            float2 c0 = *(const float2*)(ob + (size_t)tok*64 + d);
            float2 c1 = *(const float2*)(ob + (size_t)(tok+8)*64 + d);
            float v00 = (c0.x + acc[mi][ng][0]) * inv0;
            float v01 = (c0.y + acc[mi][ng][1]) * inv0;
            float v10 = (c1.x + acc[mi][ng][2]) * inv1;
            float v11 = (c1.y + acc[mi][ng][3]) * inv1;
            __nv_bfloat16 h00=__float2bfloat16(v00), h01=__float2bfloat16(v01);
            __nv_bfloat16 h10=__float2bfloat16(v10), h11=__float2bfloat16(v11);
            size_t off0 = (size_t)tok*Ec + d;
            size_t off1 = (size_t)(tok+8)*Ec + d;
            *(__nv_bfloat162*)(oh + off0) = {h00, h01};
            *(__nv_bfloat162*)(oh + off1) = {h10, h11};
            *(__nv_bfloat162*)(ol + off0) = {__float2bfloat16(v00-__bfloat162float(h00)),
                                             __float2bfloat16(v01-__bfloat162float(h01))};
            *(__nv_bfloat162*)(ol + off1) = {__float2bfloat16(v10-__bfloat162float(h10)),
                                             __float2bfloat16(v11-__bfloat162float(h11))};
        }
    }
}

// ---------------- host launcher ---------------------------------------------
extern "C" void kernel_launch(void* const* d_in, const int* in_sizes, int n_in,
                              void* d_out, int out_size)
{
    const float* x        = (const float*)d_in[0];
    const float* qkv_w    = (const float*)d_in[1];
    const float* qkv_b    = (const float*)d_in[2];
    const float* out_w    = (const float*)d_in[3];
    const float* out_b    = (const float*)d_in[4];
    const float* omega    = (const float*)d_in[5];
    const float* poly_w   = (const float*)d_in[6];
    const float* qnodes   = (const float*)d_in[7];
    const float* qweights = (const float*)d_in[8];
    float* out = (float*)d_out;

    float* qkv_ptr = 0;
    cudaGetSymbolAddress((void**)&qkv_ptr, g_qkv);
    __nv_bfloat16 *ah, *al, *wh, *wl, *w2h, *w2l;
    cudaGetSymbolAddress((void**)&ah, g_ah);
    cudaGetSymbolAddress((void**)&al, g_al);
    cudaGetSymbolAddress((void**)&wh, g_wh);
    cudaGetSymbolAddress((void**)&wl, g_wl);
    cudaGetSymbolAddress((void**)&w2h, g_w2h);
    cudaGetSymbolAddress((void**)&w2l, g_w2l);

    cudaFuncSetAttribute(gemm_mma_k, cudaFuncAttributeMaxDynamicSharedMemorySize, 2*S_STAGE);
    cudaFuncSetAttribute(features_k, cudaFuncAttributeMaxDynamicSharedMemorySize, F_SMEM);
    cudaFuncSetAttribute(attn_fused_k, cudaFuncAttributeMaxDynamicSharedMemorySize, 106496);
    cudaFuncSetAttribute(hist_mma_k, cudaFuncAttributeMaxDynamicSharedMemorySize, 38912);

    // 1) one combined split for x, qkv_w, out_w
    split3_bf16_k<<<12288, 256>>>(x, qkv_w, out_w);
    // 2) QKV GEMM (HMMA, bf16x3)
    gemm_mma_k<<<dim3(3*Ec/128, (Bc*Tc)/128), 256, 2*S_STAGE>>>(
        ah, al, wh, wl, qkv_b, qkv_ptr, 3*Ec);
    // 3) feature maps -> bf16 (hi only)
    features_k<<<dim3(BHc*NCc, 2), 256, F_SMEM>>>(omega, poly_w, qnodes, qweights);
    // 4) fused: scores (blocks 0..1023) + passA (blocks 1024..5119), concurrent
    attn_fused_k<<<5120, 256, 106496>>>();
    // 5) fused exclusive prefix
    prefix_fused_k<<<1040, 256>>>();
    // 6) history context + normalize + write bf16 rows (o2rows fused)
    hist_mma_k<<<BHc*NCc, 256, 38912>>>();
    // 7) output projection (HMMA, bf16x3)
    gemm_mma_k<<<dim3(Ec/128, (Bc*Tc)/128), 256, 2*S_STAGE>>>(
        ah, al, w2h, w2l, out_b, out, Ec);
}